// round 1
// baseline (speedup 1.0000x reference)
#include <cuda_runtime.h>

// Problem constants
#define MROWS 8192
#define NCOLS 256

// Tiling
#define BM 64
#define BN 64
#define BK 16
#define TM 8
#define TN 4
#define NTHREADS 128   // (BN/TN)=16 x (BM/TM)=8

// Scratch (device globals — no allocation allowed)
__device__ float g_d[MROWS];
__device__ float g_B[MROWS * NCOLS];

// ---------------------------------------------------------------------------
// d[i] = rsqrt(D[i,i]), with one Newton refinement for near-exact fp32
// ---------------------------------------------------------------------------
__global__ void compute_d_kernel(const float* __restrict__ D) {
    int i = blockIdx.x * blockDim.x + threadIdx.x;
    float x = D[(size_t)i * (MROWS + 1)];
    float r = rsqrtf(x);
    r = r * (1.5f - 0.5f * x * r * r);
    g_d[i] = r;
}

// ---------------------------------------------------------------------------
// Packed f32x2 helpers (Blackwell FFMA2 — 2x fp32 FMA throughput)
// ---------------------------------------------------------------------------
__device__ __forceinline__ unsigned long long pk2(float lo, float hi) {
    unsigned long long r;
    asm("mov.b64 %0, {%1, %2};" : "=l"(r) : "f"(lo), "f"(hi));
    return r;
}
__device__ __forceinline__ void upk2(unsigned long long v, float& lo, float& hi) {
    asm("mov.b64 {%0, %1}, %2;" : "=f"(lo), "=f"(hi) : "l"(v));
}
__device__ __forceinline__ void ffma2(unsigned long long& d,
                                      unsigned long long a,
                                      unsigned long long b) {
    asm("fma.rn.f32x2 %0, %1, %2, %0;" : "+l"(d) : "l"(a), "l"(b));
}

// ---------------------------------------------------------------------------
// Compute one BK-deep tile from shared into accumulators
// ---------------------------------------------------------------------------
__device__ __forceinline__ void compute_tile(const float (*Asl)[BM + 4],
                                             const float (*Bsl)[BN],
                                             int tx, int ty,
                                             unsigned long long acc[TM][2]) {
#pragma unroll
    for (int kk = 0; kk < BK; ++kk) {
        float4 bv = *(const float4*)&Bsl[kk][tx << 2];
        unsigned long long b01 = pk2(bv.x, bv.y);
        unsigned long long b23 = pk2(bv.z, bv.w);
        float4 av0 = *(const float4*)&Asl[kk][ty << 3];
        float4 av1 = *(const float4*)&Asl[kk][(ty << 3) + 4];
        float am[TM] = {av0.x, av0.y, av0.z, av0.w, av1.x, av1.y, av1.z, av1.w};
#pragma unroll
        for (int m = 0; m < TM; ++m) {
            unsigned long long aa = pk2(am[m], am[m]);
            ffma2(acc[m][0], aa, b01);
            ffma2(acc[m][1], aa, b23);
        }
    }
}

// ---------------------------------------------------------------------------
// C[row, :] = g_d[row] * (A @ Bm)[row, :]
// A: M x K (row-major, leading dim lda), Bm: K x NCOLS (row-major), C: M x NCOLS
// Double-buffered shared, register-staged global loads.
// ---------------------------------------------------------------------------
__global__ __launch_bounds__(NTHREADS)
void gemm_rowscale_kernel(const float* __restrict__ A, int lda, int K,
                          const float* __restrict__ Bm,
                          float* __restrict__ C) {
    __shared__ __align__(16) float As[2][BK][BM + 4];
    __shared__ __align__(16) float Bs[2][BK][BN];

    const int tid = threadIdx.x;
    const int tx  = tid & 15;   // n-direction thread coord (0..15)
    const int ty  = tid >> 4;   // m-direction thread coord (0..7)
    const int row0 = blockIdx.y * BM;
    const int col0 = blockIdx.x * BN;

    const float* Aptr = A + (size_t)row0 * lda;

    // A-tile load coords: idx = tid + it*128; r = idx>>2 (0..63), c = (idx&3)*4
    const int ar0 = tid >> 2;
    const int ar1 = (tid + 128) >> 2;
    const int ac  = (tid & 3) << 2;
    // B-tile load coords: r = idx>>4 (0..15), c = (idx&15)*4
    const int br0 = tid >> 4;
    const int br1 = (tid + 128) >> 4;
    const int bc  = (tid & 15) << 2;

    unsigned long long acc[TM][2];
#pragma unroll
    for (int m = 0; m < TM; ++m) { acc[m][0] = 0ull; acc[m][1] = 0ull; }

    float4 ra0, ra1, rb0, rb1;

    // Prologue: load tile 0 into regs, store to shared
    ra0 = *(const float4*)(Aptr + (size_t)ar0 * lda + ac);
    ra1 = *(const float4*)(Aptr + (size_t)ar1 * lda + ac);
    rb0 = *(const float4*)(Bm + (size_t)br0 * NCOLS + col0 + bc);
    rb1 = *(const float4*)(Bm + (size_t)br1 * NCOLS + col0 + bc);
    {
        As[0][ac + 0][ar0] = ra0.x; As[0][ac + 1][ar0] = ra0.y;
        As[0][ac + 2][ar0] = ra0.z; As[0][ac + 3][ar0] = ra0.w;
        As[0][ac + 0][ar1] = ra1.x; As[0][ac + 1][ar1] = ra1.y;
        As[0][ac + 2][ar1] = ra1.z; As[0][ac + 3][ar1] = ra1.w;
        *(float4*)&Bs[0][br0][bc] = rb0;
        *(float4*)&Bs[0][br1][bc] = rb1;
    }
    __syncthreads();

    int s = 0;
    const int ntiles = K / BK;
    for (int t = 1; t < ntiles; ++t) {
        const int k0 = t * BK;
        // Issue next tile's global loads early (latency hidden by compute)
        ra0 = *(const float4*)(Aptr + (size_t)ar0 * lda + k0 + ac);
        ra1 = *(const float4*)(Aptr + (size_t)ar1 * lda + k0 + ac);
        rb0 = *(const float4*)(Bm + (size_t)(k0 + br0) * NCOLS + col0 + bc);
        rb1 = *(const float4*)(Bm + (size_t)(k0 + br1) * NCOLS + col0 + bc);

        compute_tile(As[s], Bs[s], tx, ty, acc);

        const int d = s ^ 1;
        As[d][ac + 0][ar0] = ra0.x; As[d][ac + 1][ar0] = ra0.y;
        As[d][ac + 2][ar0] = ra0.z; As[d][ac + 3][ar0] = ra0.w;
        As[d][ac + 0][ar1] = ra1.x; As[d][ac + 1][ar1] = ra1.y;
        As[d][ac + 2][ar1] = ra1.z; As[d][ac + 3][ar1] = ra1.w;
        *(float4*)&Bs[d][br0][bc] = rb0;
        *(float4*)&Bs[d][br1][bc] = rb1;
        __syncthreads();
        s = d;
    }
    compute_tile(As[s], Bs[s], tx, ty, acc);

    // Epilogue: row scaling by g_d and vectorized store
#pragma unroll
    for (int m = 0; m < TM; ++m) {
        const int row = row0 + (ty << 3) + m;
        const float sc = g_d[row];
        float x, y, z, w;
        upk2(acc[m][0], x, y);
        upk2(acc[m][1], z, w);
        float4 o = make_float4(x * sc, y * sc, z * sc, w * sc);
        *(float4*)(C + (size_t)row * NCOLS + col0 + (tx << 2)) = o;
    }
}

// ---------------------------------------------------------------------------
// Launch: d -> B = diag(d) (H @ W) -> out = diag(d) (A @ B)
// ---------------------------------------------------------------------------
extern "C" void kernel_launch(void* const* d_in, const int* in_sizes, int n_in,
                              void* d_out, int out_size) {
    (void)in_sizes; (void)n_in; (void)out_size;
    const float* A = (const float*)d_in[0];
    const float* D = (const float*)d_in[1];
    const float* H = (const float*)d_in[2];
    const float* W = (const float*)d_in[3];
    float* out = (float*)d_out;

    float* pB = nullptr;
    cudaGetSymbolAddress((void**)&pB, g_B);

    compute_d_kernel<<<MROWS / 256, 256>>>(D);

    dim3 grid(NCOLS / BN, MROWS / BM);
    // B = diag(d) * (H @ W)   (row-scale applied in epilogue)
    gemm_rowscale_kernel<<<grid, NTHREADS>>>(H, NCOLS, NCOLS, W, pB);
    // out = diag(d) * (A @ B)
    gemm_rowscale_kernel<<<grid, NTHREADS>>>(A, MROWS, MROWS, pB, out);
}

// round 3
// speedup vs baseline: 4.2161x; 4.2161x over previous
#include <cuda_runtime.h>
#include <cuda_fp16.h>
#include <cstdint>

#define NROWS 8192
#define NCH   256
#define BM 128
#define BN 128
#define BK 64            // 64 halfs = 128B rows
#define NTHREADS 256
#define STAGE_BYTES 32768  // A tile 16KB + B tile 16KB
#define SMEM_SZ (2 * STAGE_BYTES)

// ---------------- device scratch ----------------
__device__ float  g_d[NROWS];
__device__ __half g_WhT[NCH * NCH];            // W^T fp16  [n][k]
__device__ __half g_BhT[(size_t)NCH * NROWS];  // B^T fp16  [n][m_node]

// ---------------- PTX helpers ----------------
__device__ __forceinline__ uint32_t cvta_smem(const void* p) {
    uint32_t a;
    asm("{ .reg .u64 t; cvta.to.shared.u64 t, %1; cvt.u32.u64 %0, t; }"
        : "=r"(a) : "l"(p));
    return a;
}
__device__ __forceinline__ void cp16(uint32_t saddr, const void* gaddr) {
    asm volatile("cp.async.cg.shared.global [%0], [%1], 16;"
                 :: "r"(saddr), "l"(gaddr) : "memory");
}
__device__ __forceinline__ void cp_commit() {
    asm volatile("cp.async.commit_group;" ::: "memory");
}
__device__ __forceinline__ void cp_wait0() {
    asm volatile("cp.async.wait_group 0;" ::: "memory");
}
__device__ __forceinline__ void ldmx4(uint32_t* r, uint32_t addr) {
    asm volatile("ldmatrix.sync.aligned.m8n8.x4.shared.b16 {%0,%1,%2,%3}, [%4];"
                 : "=r"(r[0]), "=r"(r[1]), "=r"(r[2]), "=r"(r[3]) : "r"(addr));
}
__device__ __forceinline__ void mma16816(float* c, const uint32_t* a,
                                         uint32_t b0, uint32_t b1) {
    asm volatile(
        "mma.sync.aligned.m16n8k16.row.col.f32.f16.f16.f32 "
        "{%0,%1,%2,%3}, {%4,%5,%6,%7}, {%8,%9}, {%0,%1,%2,%3};"
        : "+f"(c[0]), "+f"(c[1]), "+f"(c[2]), "+f"(c[3])
        : "r"(a[0]), "r"(a[1]), "r"(a[2]), "r"(a[3]), "r"(b0), "r"(b1));
}
__device__ __forceinline__ void sts128(uint32_t addr, uint32_t x, uint32_t y,
                                       uint32_t z, uint32_t w) {
    asm volatile("st.shared.v4.b32 [%0], {%1,%2,%3,%4};"
                 :: "r"(addr), "r"(x), "r"(y), "r"(z), "r"(w) : "memory");
}

// ---------------- small kernels ----------------
__global__ void compute_d_kernel(const float* __restrict__ D) {
    int i = blockIdx.x * blockDim.x + threadIdx.x;
    float x = D[(size_t)i * (NROWS + 1)];
    float r = rsqrtf(x);
    r = r * (1.5f - 0.5f * x * r * r);
    g_d[i] = r;
}
__global__ void convW_kernel(const float* __restrict__ W) {
    int k = blockIdx.x, n = threadIdx.x;
    g_WhT[n * NCH + k] = __float2half_rn(W[k * NCH + n]);
}

// ---------------------------------------------------------------------------
// C[M][N] = Aop[M][K](row-major) @ Bop[N][K](row-major, i.e. col-major operand)
// One operand is fp32 (converted to fp16 on the fly via LDG->cvt->STS),
// the other is fp16 (cp.async). F32A selects which tile the fp32 operand fills.
// EPI 0: out[m][n] = g_d[m]*acc (fp32). EPI 1: BhT[m][n] = g_d[n]*acc (fp16).
// ---------------------------------------------------------------------------
template <bool F32A, int EPI>
__global__ __launch_bounds__(NTHREADS, 1)
void gemm_hmma(const float* __restrict__ f32op, int ld32,
               const __half* __restrict__ f16op, int ld16,
               int ktiles, float* __restrict__ dstf, __half* __restrict__ dsth) {
    extern __shared__ __align__(16) char smem_raw[];
    const uint32_t smem = cvta_smem(smem_raw);

    const int tid  = threadIdx.x;
    const int lane = tid & 31;
    const int wid  = tid >> 5;
    const int wm   = (wid & 1) * 64;   // warp m offset
    const int wn   = (wid >> 1) * 32;  // warp n offset

    const int m0 = blockIdx.y * BM;
    const int n0 = blockIdx.x * BN;

    const int base32 = F32A ? m0 : n0;
    const int base16 = F32A ? n0 : m0;
    const uint32_t off32 = F32A ? 0u : 16384u;   // fp32-fed tile region
    const uint32_t off16 = F32A ? 16384u : 0u;   // fp16-fed tile region
    const uint32_t offA  = F32A ? off32 : off16; // A region (M side)
    const uint32_t offB  = F32A ? off16 : off32; // B region (N side)

    // ---- loader geometry: thread -> (row = tid>>1, half-row seg = tid&1)
    const int lrow = tid >> 1;
    const int lseg = tid & 1;
    const float* g32 = f32op + (size_t)(base32 + lrow) * ld32 + lseg * 32;
    const __half* g16 = f16op + (size_t)(base16 + lrow) * ld16 + lseg * 32;
    const uint32_t srow = (uint32_t)lrow * 128u;
    const int rmask = lrow & 7;

    float4 pf[8];

#define LDG32(t)                                                               \
    do {                                                                       \
        const float4* p = (const float4*)(g32 + (size_t)(t) * BK);             \
        _Pragma("unroll") for (int j = 0; j < 8; ++j) pf[j] = __ldg(p + j);    \
    } while (0)

#define STS32(stg)                                                             \
    do {                                                                       \
        uint32_t db = smem + (stg) * STAGE_BYTES + off32 + srow;               \
        _Pragma("unroll") for (int c = 0; c < 4; ++c) {                        \
            __half2 h0 = __floats2half2_rn(pf[2 * c].x, pf[2 * c].y);          \
            __half2 h1 = __floats2half2_rn(pf[2 * c].z, pf[2 * c].w);          \
            __half2 h2 = __floats2half2_rn(pf[2 * c + 1].x, pf[2 * c + 1].y);  \
            __half2 h3 = __floats2half2_rn(pf[2 * c + 1].z, pf[2 * c + 1].w);  \
            uint32_t ch = (uint32_t)((lseg * 4 + c) ^ rmask);                  \
            sts128(db + ch * 16u, *(uint32_t*)&h0, *(uint32_t*)&h1,            \
                   *(uint32_t*)&h2, *(uint32_t*)&h3);                          \
        }                                                                      \
    } while (0)

#define CP16T(t, stg)                                                          \
    do {                                                                       \
        uint32_t db = smem + (stg) * STAGE_BYTES + off16 + srow;               \
        const __half* p = g16 + (size_t)(t) * BK;                              \
        _Pragma("unroll") for (int j = 0; j < 4; ++j) {                        \
            uint32_t ch = (uint32_t)((lseg * 4 + j) ^ rmask);                  \
            cp16(db + ch * 16u, p + j * 8);                                    \
        }                                                                      \
    } while (0)

    // ---- accumulators
    float acc[4][4][4];
#pragma unroll
    for (int i = 0; i < 4; ++i)
#pragma unroll
        for (int j = 0; j < 4; ++j)
#pragma unroll
            for (int q = 0; q < 4; ++q) acc[i][j][q] = 0.0f;

    // ---- ldmatrix row bases (byte offsets within a tile region)
    const int lr8 = (lane & 7) + ((lane >> 3) & 1) * 8;
    uint32_t rowA[4], rowB[2];
#pragma unroll
    for (int mt = 0; mt < 4; ++mt) rowA[mt] = (uint32_t)(wm + mt * 16 + lr8) * 128u;
#pragma unroll
    for (int i = 0; i < 2; ++i) rowB[i] = (uint32_t)(wn + i * 16 + lr8) * 128u;
    const uint32_t lmask = (uint32_t)(lane & 7);
    const uint32_t khalf = (uint32_t)(lane >> 4);  // 0 or 1

#define COMPUTE(stg)                                                           \
    do {                                                                       \
        uint32_t sa = smem + (stg) * STAGE_BYTES + offA;                       \
        uint32_t sb = smem + (stg) * STAGE_BYTES + offB;                       \
        _Pragma("unroll") for (int ks = 0; ks < 4; ++ks) {                     \
            uint32_t pa = ((ks * 2 + khalf) ^ lmask) * 16u;                    \
            uint32_t a[4][4], b[2][4];                                         \
            _Pragma("unroll") for (int mt = 0; mt < 4; ++mt)                   \
                ldmx4(a[mt], sa + rowA[mt] + pa);                              \
            _Pragma("unroll") for (int i = 0; i < 2; ++i)                      \
                ldmx4(b[i], sb + rowB[i] + pa);                                \
            _Pragma("unroll") for (int mt = 0; mt < 4; ++mt)                   \
                _Pragma("unroll") for (int j = 0; j < 4; ++j)                  \
                    mma16816(acc[mt][j], a[mt], b[j >> 1][j & 1],              \
                             b[j >> 1][2 + (j & 1)]);                          \
        }                                                                      \
    } while (0)

    // ---- pipeline
    const int T = ktiles;
    LDG32(0);
    CP16T(0, 0);
    cp_commit();
    STS32(0);
    if (T > 1) LDG32(1);
    cp_wait0();
    __syncthreads();

    int s = 0;
    for (int t = 0; t < T; ++t) {
        if (t + 1 < T) { CP16T(t + 1, s ^ 1); cp_commit(); }
        COMPUTE(s);
        if (t + 1 < T) {
            STS32(s ^ 1);
            if (t + 2 < T) LDG32(t + 2);
            cp_wait0();
        }
        __syncthreads();
        s ^= 1;
    }

    // ---- epilogue
    const int er = lane >> 2;          // row within m16
    const int ec = (lane & 3) * 2;     // col pair within n8
#pragma unroll
    for (int mt = 0; mt < 4; ++mt) {
        const int r0 = m0 + wm + mt * 16 + er;
#pragma unroll
        for (int j = 0; j < 4; ++j) {
            const int c = n0 + wn + j * 8 + ec;
            float* a = acc[mt][j];
            if (EPI == 0) {
                float s0 = g_d[r0], s1 = g_d[r0 + 8];
                *(float2*)(dstf + (size_t)r0 * NCH + c) =
                    make_float2(a[0] * s0, a[1] * s0);
                *(float2*)(dstf + (size_t)(r0 + 8) * NCH + c) =
                    make_float2(a[2] * s1, a[3] * s1);
            } else {
                float s0 = g_d[c], s1 = g_d[c + 1];
                __half2 h0 = __floats2half2_rn(a[0] * s0, a[1] * s1);
                __half2 h1 = __floats2half2_rn(a[2] * s0, a[3] * s1);
                *(__half2*)(dsth + (size_t)r0 * NROWS + c) = h0;
                *(__half2*)(dsth + (size_t)(r0 + 8) * NROWS + c) = h1;
            }
        }
    }
#undef LDG32
#undef STS32
#undef CP16T
#undef COMPUTE
}

// ---------------- launch ----------------
extern "C" void kernel_launch(void* const* d_in, const int* in_sizes, int n_in,
                              void* d_out, int out_size) {
    (void)in_sizes; (void)n_in; (void)out_size;
    const float* A = (const float*)d_in[0];
    const float* D = (const float*)d_in[1];
    const float* H = (const float*)d_in[2];
    const float* W = (const float*)d_in[3];
    float* out = (float*)d_out;

    __half *pWhT, *pBhT;
    cudaGetSymbolAddress((void**)&pWhT, g_WhT);
    cudaGetSymbolAddress((void**)&pBhT, g_BhT);

    cudaFuncSetAttribute(gemm_hmma<false, 1>,
                         cudaFuncAttributeMaxDynamicSharedMemorySize, SMEM_SZ);
    cudaFuncSetAttribute(gemm_hmma<true, 0>,
                         cudaFuncAttributeMaxDynamicSharedMemorySize, SMEM_SZ);

    compute_d_kernel<<<NROWS / 256, 256>>>(D);
    convW_kernel<<<NCH, NCH>>>(W);

    // B^T[n][m] = d[m] * (W^T @ H^T)[n][m]   — M-dim=256(n), N-dim=8192(m), K=256
    // A-op = WhT (fp16), B-op = H (fp32, converted on the fly)
    gemm_hmma<false, 1><<<dim3(NROWS / BN, NCH / BM), NTHREADS, SMEM_SZ>>>(
        H, NCH, pWhT, NCH, NCH / BK, nullptr, pBhT);

    // out[m][n] = d[m] * (A @ B)[m][n]       — M-dim=8192, N-dim=256, K=8192
    // A-op = A (fp32, converted on the fly), B-op = BhT (fp16)
    gemm_hmma<true, 0><<<dim3(NCH / BN, NROWS / BM), NTHREADS, SMEM_SZ>>>(
        A, NROWS, pBhT, NROWS, NROWS / BK, out, nullptr);
}

// round 4
// speedup vs baseline: 4.5062x; 1.0688x over previous
#include <cuda_runtime.h>
#include <cuda_fp16.h>
#include <cstdint>

#define NROWS 8192
#define NCH   256

// ---- GEMM1 (small) tiling ----
#define BM 128
#define BN 128
#define BK 64
#define NTHREADS 256
#define STAGE_BYTES 32768
#define SMEM_SZ (2 * STAGE_BYTES)

// ---- GEMM2 (big) tiling ----
#define BM2 128
#define BN2 256
#define BK2 64
#define KSPLIT 2
#define KLEN (NROWS / KSPLIT)      // 4096
#define NSTG 3
#define STG2 49152                 // A 16KB + B 32KB
#define SMEM2 (NSTG * STG2)        // 147456

// ---------------- device scratch ----------------
__device__ float  g_d[NROWS];
__device__ __half g_WhT[NCH * NCH];            // W^T fp16 [n][k]
__device__ __half g_BhT[(size_t)NCH * NROWS];  // B^T fp16 [n][m]
__device__ float  g_P[(size_t)KSPLIT * NROWS * NCH];

// ---------------- PTX helpers ----------------
__device__ __forceinline__ uint32_t cvta_smem(const void* p) {
    uint32_t a;
    asm("{ .reg .u64 t; cvta.to.shared.u64 t, %1; cvt.u32.u64 %0, t; }"
        : "=r"(a) : "l"(p));
    return a;
}
__device__ __forceinline__ void cp16(uint32_t saddr, const void* gaddr) {
    asm volatile("cp.async.cg.shared.global [%0], [%1], 16;"
                 :: "r"(saddr), "l"(gaddr) : "memory");
}
__device__ __forceinline__ void cp_commit() {
    asm volatile("cp.async.commit_group;" ::: "memory");
}
__device__ __forceinline__ void cp_wait0() {
    asm volatile("cp.async.wait_group 0;" ::: "memory");
}
__device__ __forceinline__ void cp_wait1() {
    asm volatile("cp.async.wait_group 1;" ::: "memory");
}
__device__ __forceinline__ void ldmx4(uint32_t* r, uint32_t addr) {
    asm volatile("ldmatrix.sync.aligned.m8n8.x4.shared.b16 {%0,%1,%2,%3}, [%4];"
                 : "=r"(r[0]), "=r"(r[1]), "=r"(r[2]), "=r"(r[3]) : "r"(addr));
}
__device__ __forceinline__ void mma16816(float* c, const uint32_t* a,
                                         uint32_t b0, uint32_t b1) {
    asm volatile(
        "mma.sync.aligned.m16n8k16.row.col.f32.f16.f16.f32 "
        "{%0,%1,%2,%3}, {%4,%5,%6,%7}, {%8,%9}, {%0,%1,%2,%3};"
        : "+f"(c[0]), "+f"(c[1]), "+f"(c[2]), "+f"(c[3])
        : "r"(a[0]), "r"(a[1]), "r"(a[2]), "r"(a[3]), "r"(b0), "r"(b1));
}
__device__ __forceinline__ void sts128(uint32_t addr, uint32_t x, uint32_t y,
                                       uint32_t z, uint32_t w) {
    asm volatile("st.shared.v4.b32 [%0], {%1,%2,%3,%4};"
                 :: "r"(addr), "r"(x), "r"(y), "r"(z), "r"(w) : "memory");
}

// ---------------- small kernels ----------------
__global__ void compute_d_kernel(const float* __restrict__ D) {
    int i = blockIdx.x * blockDim.x + threadIdx.x;
    float x = D[(size_t)i * (NROWS + 1)];
    float r = rsqrtf(x);
    r = r * (1.5f - 0.5f * x * r * r);
    g_d[i] = r;
}
__global__ void convW_kernel(const float* __restrict__ W) {
    int k = blockIdx.x, n = threadIdx.x;
    g_WhT[n * NCH + k] = __float2half_rn(W[k * NCH + n]);
}
// out[m][n] = d[m] * (P0[m][n] + P1[m][n])
__global__ void reduce_kernel(float* __restrict__ out) {
    size_t base = ((size_t)blockIdx.x * blockDim.x + threadIdx.x) * 4;
    int row = (int)(base >> 8);
    float sc = g_d[row];
    float4 a = *(const float4*)(g_P + base);
    float4 b = *(const float4*)(g_P + (size_t)NROWS * NCH + base);
    float4 o;
    o.x = sc * (a.x + b.x);
    o.y = sc * (a.y + b.y);
    o.z = sc * (a.z + b.z);
    o.w = sc * (a.w + b.w);
    *(float4*)(out + base) = o;
}

// ---------------------------------------------------------------------------
// GEMM1 (2-stage, from R3): BhT[n][m] = d[m] * (W^T @ H^T)[n][m], fp16 out.
// A-op = WhT fp16 (cp.async), B-op = H fp32 (LDG->cvt->STS).
// ---------------------------------------------------------------------------
__global__ __launch_bounds__(NTHREADS, 1)
void gemm1_hmma(const float* __restrict__ f32op, int ld32,
                const __half* __restrict__ f16op, int ld16,
                int ktiles, __half* __restrict__ dsth) {
    extern __shared__ __align__(16) char smem_raw[];
    const uint32_t smem = cvta_smem(smem_raw);

    const int tid  = threadIdx.x;
    const int lane = tid & 31;
    const int wid  = tid >> 5;
    const int wm   = (wid & 1) * 64;
    const int wn   = (wid >> 1) * 32;

    const int m0 = blockIdx.y * BM;   // n-channel dim
    const int n0 = blockIdx.x * BN;   // node dim

    const uint32_t off32 = 16384u;    // fp32-fed tile (B side here)
    const uint32_t off16 = 0u;        // fp16-fed tile (A side here)

    const int lrow = tid >> 1;
    const int lseg = tid & 1;
    const float* g32 = f32op + (size_t)(n0 + lrow) * ld32 + lseg * 32;
    const __half* g16 = f16op + (size_t)(m0 + lrow) * ld16 + lseg * 32;
    const uint32_t srow = (uint32_t)lrow * 128u;
    const int rmask = lrow & 7;

    float4 pf[8];

#define LDG32(t)                                                               \
    do {                                                                       \
        const float4* p = (const float4*)(g32 + (size_t)(t) * BK);             \
        _Pragma("unroll") for (int j = 0; j < 8; ++j) pf[j] = __ldg(p + j);    \
    } while (0)
#define STS32(stg)                                                             \
    do {                                                                       \
        uint32_t db = smem + (stg) * STAGE_BYTES + off32 + srow;               \
        _Pragma("unroll") for (int c = 0; c < 4; ++c) {                        \
            __half2 h0 = __floats2half2_rn(pf[2 * c].x, pf[2 * c].y);          \
            __half2 h1 = __floats2half2_rn(pf[2 * c].z, pf[2 * c].w);          \
            __half2 h2 = __floats2half2_rn(pf[2 * c + 1].x, pf[2 * c + 1].y);  \
            __half2 h3 = __floats2half2_rn(pf[2 * c + 1].z, pf[2 * c + 1].w);  \
            uint32_t ch = (uint32_t)((lseg * 4 + c) ^ rmask);                  \
            sts128(db + ch * 16u, *(uint32_t*)&h0, *(uint32_t*)&h1,            \
                   *(uint32_t*)&h2, *(uint32_t*)&h3);                          \
        }                                                                      \
    } while (0)
#define CP16T(t, stg)                                                          \
    do {                                                                       \
        uint32_t db = smem + (stg) * STAGE_BYTES + off16 + srow;               \
        const __half* p = g16 + (size_t)(t) * BK;                              \
        _Pragma("unroll") for (int j = 0; j < 4; ++j) {                        \
            uint32_t ch = (uint32_t)((lseg * 4 + j) ^ rmask);                  \
            cp16(db + ch * 16u, p + j * 8);                                    \
        }                                                                      \
    } while (0)

    float acc[4][4][4];
#pragma unroll
    for (int i = 0; i < 4; ++i)
#pragma unroll
        for (int j = 0; j < 4; ++j)
#pragma unroll
            for (int q = 0; q < 4; ++q) acc[i][j][q] = 0.0f;

    const int lr8 = (lane & 7) + ((lane >> 3) & 1) * 8;
    uint32_t rowA[4], rowB[2];
#pragma unroll
    for (int mt = 0; mt < 4; ++mt) rowA[mt] = (uint32_t)(wm + mt * 16 + lr8) * 128u;
#pragma unroll
    for (int i = 0; i < 2; ++i) rowB[i] = (uint32_t)(wn + i * 16 + lr8) * 128u;
    const uint32_t lmask = (uint32_t)(lane & 7);
    const uint32_t khalf = (uint32_t)(lane >> 4);

#define COMPUTE1(stg)                                                          \
    do {                                                                       \
        uint32_t sa = smem + (stg) * STAGE_BYTES + off16;                      \
        uint32_t sb = smem + (stg) * STAGE_BYTES + off32;                      \
        _Pragma("unroll") for (int ks = 0; ks < 4; ++ks) {                     \
            uint32_t pa = ((ks * 2 + khalf) ^ lmask) * 16u;                    \
            uint32_t a[4][4], b[2][4];                                         \
            _Pragma("unroll") for (int mt = 0; mt < 4; ++mt)                   \
                ldmx4(a[mt], sa + rowA[mt] + pa);                              \
            _Pragma("unroll") for (int i = 0; i < 2; ++i)                      \
                ldmx4(b[i], sb + rowB[i] + pa);                                \
            _Pragma("unroll") for (int mt = 0; mt < 4; ++mt)                   \
                _Pragma("unroll") for (int j = 0; j < 4; ++j)                  \
                    mma16816(acc[mt][j], a[mt], b[j >> 1][j & 1],              \
                             b[j >> 1][2 + (j & 1)]);                          \
        }                                                                      \
    } while (0)

    const int T = ktiles;
    LDG32(0);
    CP16T(0, 0);
    cp_commit();
    STS32(0);
    if (T > 1) LDG32(1);
    cp_wait0();
    __syncthreads();

    int s = 0;
    for (int t = 0; t < T; ++t) {
        if (t + 1 < T) { CP16T(t + 1, s ^ 1); cp_commit(); }
        COMPUTE1(s);
        if (t + 1 < T) {
            STS32(s ^ 1);
            if (t + 2 < T) LDG32(t + 2);
            cp_wait0();
        }
        __syncthreads();
        s ^= 1;
    }

    const int er = lane >> 2;
    const int ec = (lane & 3) * 2;
#pragma unroll
    for (int mt = 0; mt < 4; ++mt) {
        const int r0 = m0 + wm + mt * 16 + er;
#pragma unroll
        for (int j = 0; j < 4; ++j) {
            const int c = n0 + wn + j * 8 + ec;
            float* a = acc[mt][j];
            float s0 = g_d[c], s1 = g_d[c + 1];
            __half2 h0 = __floats2half2_rn(a[0] * s0, a[1] * s1);
            __half2 h1 = __floats2half2_rn(a[2] * s0, a[3] * s1);
            *(__half2*)(dsth + (size_t)r0 * NROWS + c) = h0;
            *(__half2*)(dsth + (size_t)(r0 + 8) * NROWS + c) = h1;
        }
    }
#undef LDG32
#undef STS32
#undef CP16T
#undef COMPUTE1
}

// ---------------------------------------------------------------------------
// GEMM2 (3-stage, 128x256 CTA tile, 64x64 warp tile, K-split):
// P[z][m][n] = A[m, z*KLEN : (z+1)*KLEN] @ B[z-slice][n]
// A fp32 (LDG->cvt->STS, off critical path), B = g_BhT fp16 (cp.async).
// ---------------------------------------------------------------------------
__global__ __launch_bounds__(256, 1)
void gemm2_hmma(const float* __restrict__ A, float* __restrict__ P) {
    extern __shared__ __align__(16) char smem_raw[];
    const uint32_t smem = cvta_smem(smem_raw);

    const int tid  = threadIdx.x;
    const int lane = tid & 31;
    const int wid  = tid >> 5;
    const int wm   = (wid & 1) * 64;   // 2 warps in M
    const int wn   = (wid >> 1) * 64;  // 4 warps in N

    const int m0 = blockIdx.x * BM2;
    const int kb = blockIdx.y * KLEN;

    // A loader: 2 threads/row, row = tid>>1, half h = tid&1 (32 floats each)
    const int arow = tid >> 1;
    const int ah   = tid & 1;
    const float* gA = A + (size_t)(m0 + arow) * NROWS + kb + ah * 32;
    const uint32_t arow_off = (uint32_t)arow * 128u;
    const int armask = arow & 7;

    // B loader: 1 thread/row (256 rows), 8 x 16B chunks each
    const __half* gB = g_BhT + (size_t)tid * NROWS + kb;
    const uint32_t brow_off = 16384u + (uint32_t)tid * 128u;
    const int brmask = tid & 7;

    float4 pf[8];

#define LDGA(t)                                                                \
    do {                                                                       \
        const float4* p = (const float4*)(gA + (size_t)(t) * BK2);             \
        _Pragma("unroll") for (int j = 0; j < 8; ++j) pf[j] = __ldg(p + j);    \
    } while (0)
#define STSA(stg)                                                              \
    do {                                                                       \
        uint32_t db = smem + (stg) * STG2 + arow_off;                          \
        _Pragma("unroll") for (int c = 0; c < 4; ++c) {                        \
            __half2 h0 = __floats2half2_rn(pf[2 * c].x, pf[2 * c].y);          \
            __half2 h1 = __floats2half2_rn(pf[2 * c].z, pf[2 * c].w);          \
            __half2 h2 = __floats2half2_rn(pf[2 * c + 1].x, pf[2 * c + 1].y);  \
            __half2 h3 = __floats2half2_rn(pf[2 * c + 1].z, pf[2 * c + 1].w);  \
            uint32_t ch = (uint32_t)((ah * 4 + c) ^ armask);                   \
            sts128(db + ch * 16u, *(uint32_t*)&h0, *(uint32_t*)&h1,            \
                   *(uint32_t*)&h2, *(uint32_t*)&h3);                          \
        }                                                                      \
    } while (0)
#define CPB(stg, t)                                                            \
    do {                                                                       \
        uint32_t db = smem + (stg) * STG2 + brow_off;                          \
        const __half* p = gB + (size_t)(t) * BK2;                              \
        _Pragma("unroll") for (int j = 0; j < 8; ++j) {                        \
            uint32_t ch = (uint32_t)(j ^ brmask);                              \
            cp16(db + ch * 16u, p + j * 8);                                    \
        }                                                                      \
    } while (0)

    float acc[4][8][4];
#pragma unroll
    for (int i = 0; i < 4; ++i)
#pragma unroll
        for (int j = 0; j < 8; ++j)
#pragma unroll
            for (int q = 0; q < 4; ++q) acc[i][j][q] = 0.0f;

    const int lr8 = (lane & 7) + ((lane >> 3) & 1) * 8;
    uint32_t rowA[4], rowB[4];
#pragma unroll
    for (int mt = 0; mt < 4; ++mt) rowA[mt] = (uint32_t)(wm + mt * 16 + lr8) * 128u;
#pragma unroll
    for (int nt = 0; nt < 4; ++nt)
        rowB[nt] = 16384u + (uint32_t)(wn + nt * 16 + lr8) * 128u;
    const uint32_t lmask = (uint32_t)(lane & 7);
    const uint32_t khalf = (uint32_t)(lane >> 4);

#define COMPUTE2(stg)                                                          \
    do {                                                                       \
        uint32_t sb0 = smem + (stg) * STG2;                                    \
        _Pragma("unroll") for (int ks = 0; ks < 4; ++ks) {                     \
            uint32_t pa = ((ks * 2 + khalf) ^ lmask) * 16u;                    \
            uint32_t a[4][4], b[4][4];                                         \
            _Pragma("unroll") for (int mt = 0; mt < 4; ++mt)                   \
                ldmx4(a[mt], sb0 + rowA[mt] + pa);                             \
            _Pragma("unroll") for (int nt = 0; nt < 4; ++nt)                   \
                ldmx4(b[nt], sb0 + rowB[nt] + pa);                             \
            _Pragma("unroll") for (int mt = 0; mt < 4; ++mt)                   \
                _Pragma("unroll") for (int j = 0; j < 8; ++j)                  \
                    mma16816(acc[mt][j], a[mt], b[j >> 1][j & 1],              \
                             b[j >> 1][2 + (j & 1)]);                          \
        }                                                                      \
    } while (0)

    const int T = KLEN / BK2;  // 64

    // prologue
    LDGA(0);
    CPB(0, 0); cp_commit();                   // g0
    STSA(0);
    LDGA(1);
    CPB(1, 1); cp_commit();                   // g1
    STSA(1);
    LDGA(2);

    int s = 0;
    for (int t = 0; t < T; ++t) {
        cp_wait1();
        __syncthreads();
        const int ts = t + 2;
        if (ts < T) {
            const int stg = (s + 2 >= NSTG) ? (s + 2 - NSTG) : (s + 2);
            STSA(stg);                        // pf holds tile ts
            if (t + 3 < T) LDGA(t + 3);
            CPB(stg, ts);
        }
        cp_commit();
        COMPUTE2(s);
        s = (s + 1 == NSTG) ? 0 : (s + 1);
    }

    // epilogue -> fp32 partials
    float* Pz = P + (size_t)blockIdx.y * NROWS * NCH;
    const int er = lane >> 2;
    const int ec = (lane & 3) * 2;
#pragma unroll
    for (int mt = 0; mt < 4; ++mt) {
        const int r0 = m0 + wm + mt * 16 + er;
#pragma unroll
        for (int j = 0; j < 8; ++j) {
            const int c = wn + j * 8 + ec;
            float* a = acc[mt][j];
            *(float2*)(Pz + (size_t)r0 * NCH + c) = make_float2(a[0], a[1]);
            *(float2*)(Pz + (size_t)(r0 + 8) * NCH + c) = make_float2(a[2], a[3]);
        }
    }
#undef LDGA
#undef STSA
#undef CPB
#undef COMPUTE2
}

// ---------------- launch ----------------
extern "C" void kernel_launch(void* const* d_in, const int* in_sizes, int n_in,
                              void* d_out, int out_size) {
    (void)in_sizes; (void)n_in; (void)out_size;
    const float* A = (const float*)d_in[0];
    const float* D = (const float*)d_in[1];
    const float* H = (const float*)d_in[2];
    const float* W = (const float*)d_in[3];
    float* out = (float*)d_out;

    __half *pWhT, *pBhT;
    float* pP;
    cudaGetSymbolAddress((void**)&pWhT, g_WhT);
    cudaGetSymbolAddress((void**)&pBhT, g_BhT);
    cudaGetSymbolAddress((void**)&pP, g_P);

    cudaFuncSetAttribute(gemm1_hmma, cudaFuncAttributeMaxDynamicSharedMemorySize,
                         SMEM_SZ);
    cudaFuncSetAttribute(gemm2_hmma, cudaFuncAttributeMaxDynamicSharedMemorySize,
                         SMEM2);

    compute_d_kernel<<<NROWS / 256, 256>>>(D);
    convW_kernel<<<NCH, NCH>>>(W);

    // BhT[n][m] = d[m] * (W^T @ H^T)[n][m]
    gemm1_hmma<<<dim3(NROWS / BN, NCH / BM), NTHREADS, SMEM_SZ>>>(
        H, NCH, pWhT, NCH, NCH / BK, pBhT);

    // P[z] = A[:, z-slice] @ B[z-slice, :]
    gemm2_hmma<<<dim3(NROWS / BM2, KSPLIT), 256, SMEM2>>>(A, pP);

    // out = diag(d) * (P0 + P1)
    reduce_kernel<<<(NROWS * NCH) / 1024, 256>>>(out);
}

// round 6
// speedup vs baseline: 5.6073x; 1.2444x over previous
#include <cuda_runtime.h>
#include <cuda_fp16.h>
#include <cstdint>

#define NROWS 8192
#define NCH   256

// ---- GEMM1 (small) tiling ----
#define BM 128
#define BN 128
#define BK 64
#define NTHREADS 256
#define STAGE_BYTES 32768
#define SMEM_SZ (2 * STAGE_BYTES)

// ---- GEMM2 (big) tiling ----
#define BM2 128
#define BN2 256
#define BK2 64
#define NTH2 512
#define KSPLIT 2
#define KLEN (NROWS / KSPLIT)      // 4096
#define NSTG 3
#define STG2 49152                 // A 16KB + B 32KB
#define SMEM2 (NSTG * STG2)        // 147456

// ---------------- device scratch ----------------
__device__ float  g_d[NROWS];
__device__ __half g_WhT[NCH * NCH];            // W^T fp16 [n][k]
__device__ __half g_BhT[(size_t)NCH * NROWS];  // B^T fp16 [n][m]
__device__ float  g_P[(size_t)KSPLIT * NROWS * NCH];

// ---------------- PTX helpers ----------------
__device__ __forceinline__ uint32_t cvta_smem(const void* p) {
    uint32_t a;
    asm("{ .reg .u64 t; cvta.to.shared.u64 t, %1; cvt.u32.u64 %0, t; }"
        : "=r"(a) : "l"(p));
    return a;
}
__device__ __forceinline__ void cp16(uint32_t saddr, const void* gaddr) {
    asm volatile("cp.async.cg.shared.global [%0], [%1], 16;"
                 :: "r"(saddr), "l"(gaddr) : "memory");
}
__device__ __forceinline__ void cp_commit() {
    asm volatile("cp.async.commit_group;" ::: "memory");
}
__device__ __forceinline__ void cp_wait0() {
    asm volatile("cp.async.wait_group 0;" ::: "memory");
}
__device__ __forceinline__ void cp_wait1() {
    asm volatile("cp.async.wait_group 1;" ::: "memory");
}
__device__ __forceinline__ void ldmx4(uint32_t* r, uint32_t addr) {
    asm volatile("ldmatrix.sync.aligned.m8n8.x4.shared.b16 {%0,%1,%2,%3}, [%4];"
                 : "=r"(r[0]), "=r"(r[1]), "=r"(r[2]), "=r"(r[3]) : "r"(addr));
}
__device__ __forceinline__ void mma16816(float* c, const uint32_t* a,
                                         uint32_t b0, uint32_t b1) {
    asm volatile(
        "mma.sync.aligned.m16n8k16.row.col.f32.f16.f16.f32 "
        "{%0,%1,%2,%3}, {%4,%5,%6,%7}, {%8,%9}, {%0,%1,%2,%3};"
        : "+f"(c[0]), "+f"(c[1]), "+f"(c[2]), "+f"(c[3])
        : "r"(a[0]), "r"(a[1]), "r"(a[2]), "r"(a[3]), "r"(b0), "r"(b1));
}
__device__ __forceinline__ void sts128(uint32_t addr, uint32_t x, uint32_t y,
                                       uint32_t z, uint32_t w) {
    asm volatile("st.shared.v4.b32 [%0], {%1,%2,%3,%4};"
                 :: "r"(addr), "r"(x), "r"(y), "r"(z), "r"(w) : "memory");
}

// ---------------- small kernels ----------------
__global__ void compute_d_kernel(const float* __restrict__ D) {
    int i = blockIdx.x * blockDim.x + threadIdx.x;
    float x = D[(size_t)i * (NROWS + 1)];
    float r = rsqrtf(x);
    r = r * (1.5f - 0.5f * x * r * r);
    g_d[i] = r;
}
__global__ void convW_kernel(const float* __restrict__ W) {
    int k = blockIdx.x, n = threadIdx.x;
    g_WhT[n * NCH + k] = __float2half_rn(W[k * NCH + n]);
}
// out[m][n] = d[m] * (P0[m][n] + P1[m][n])
__global__ void reduce_kernel(float* __restrict__ out) {
    size_t base = ((size_t)blockIdx.x * blockDim.x + threadIdx.x) * 4;
    int row = (int)(base >> 8);
    float sc = g_d[row];
    float4 a = *(const float4*)(g_P + base);
    float4 b = *(const float4*)(g_P + (size_t)NROWS * NCH + base);
    float4 o;
    o.x = sc * (a.x + b.x);
    o.y = sc * (a.y + b.y);
    o.z = sc * (a.z + b.z);
    o.w = sc * (a.w + b.w);
    *(float4*)(out + base) = o;
}

// ---------------------------------------------------------------------------
// GEMM1 (2-stage): BhT[n][m] = d[m] * (W^T @ H^T)[n][m], fp16 out.
// A-op = WhT fp16 (cp.async), B-op = H fp32 (LDG->cvt->STS).
// ---------------------------------------------------------------------------
__global__ __launch_bounds__(NTHREADS, 1)
void gemm1_hmma(const float* __restrict__ f32op, int ld32,
                const __half* __restrict__ f16op, int ld16,
                int ktiles, __half* __restrict__ dsth) {
    extern __shared__ __align__(16) char smem_raw[];
    const uint32_t smem = cvta_smem(smem_raw);

    const int tid  = threadIdx.x;
    const int lane = tid & 31;
    const int wid  = tid >> 5;
    const int wm   = (wid & 1) * 64;
    const int wn   = (wid >> 1) * 32;

    const int m0 = blockIdx.y * BM;   // n-channel dim
    const int n0 = blockIdx.x * BN;   // node dim

    const uint32_t off32 = 16384u;
    const uint32_t off16 = 0u;

    const int lrow = tid >> 1;
    const int lseg = tid & 1;
    const float* g32 = f32op + (size_t)(n0 + lrow) * ld32 + lseg * 32;
    const __half* g16 = f16op + (size_t)(m0 + lrow) * ld16 + lseg * 32;
    const uint32_t srow = (uint32_t)lrow * 128u;
    const int rmask = lrow & 7;

    float4 pf[8];

#define LDG32(t)                                                               \
    do {                                                                       \
        const float4* p = (const float4*)(g32 + (size_t)(t) * BK);             \
        _Pragma("unroll") for (int j = 0; j < 8; ++j) pf[j] = __ldg(p + j);    \
    } while (0)
#define STS32(stg)                                                             \
    do {                                                                       \
        uint32_t db = smem + (stg) * STAGE_BYTES + off32 + srow;               \
        _Pragma("unroll") for (int c = 0; c < 4; ++c) {                        \
            __half2 h0 = __floats2half2_rn(pf[2 * c].x, pf[2 * c].y);          \
            __half2 h1 = __floats2half2_rn(pf[2 * c].z, pf[2 * c].w);          \
            __half2 h2 = __floats2half2_rn(pf[2 * c + 1].x, pf[2 * c + 1].y);  \
            __half2 h3 = __floats2half2_rn(pf[2 * c + 1].z, pf[2 * c + 1].w);  \
            uint32_t ch = (uint32_t)((lseg * 4 + c) ^ rmask);                  \
            sts128(db + ch * 16u, *(uint32_t*)&h0, *(uint32_t*)&h1,            \
                   *(uint32_t*)&h2, *(uint32_t*)&h3);                          \
        }                                                                      \
    } while (0)
#define CP16T(t, stg)                                                          \
    do {                                                                       \
        uint32_t db = smem + (stg) * STAGE_BYTES + off16 + srow;               \
        const __half* p = g16 + (size_t)(t) * BK;                              \
        _Pragma("unroll") for (int j = 0; j < 4; ++j) {                        \
            uint32_t ch = (uint32_t)((lseg * 4 + j) ^ rmask);                  \
            cp16(db + ch * 16u, p + j * 8);                                    \
        }                                                                      \
    } while (0)

    float acc[4][4][4];
#pragma unroll
    for (int i = 0; i < 4; ++i)
#pragma unroll
        for (int j = 0; j < 4; ++j)
#pragma unroll
            for (int q = 0; q < 4; ++q) acc[i][j][q] = 0.0f;

    const int lr8 = (lane & 7) + ((lane >> 3) & 1) * 8;
    uint32_t rowA[4], rowB[2];
#pragma unroll
    for (int mt = 0; mt < 4; ++mt) rowA[mt] = (uint32_t)(wm + mt * 16 + lr8) * 128u;
#pragma unroll
    for (int i = 0; i < 2; ++i) rowB[i] = (uint32_t)(wn + i * 16 + lr8) * 128u;
    const uint32_t lmask = (uint32_t)(lane & 7);
    const uint32_t khalf = (uint32_t)(lane >> 4);

#define COMPUTE1(stg)                                                          \
    do {                                                                       \
        uint32_t sa = smem + (stg) * STAGE_BYTES + off16;                      \
        uint32_t sb = smem + (stg) * STAGE_BYTES + off32;                      \
        _Pragma("unroll") for (int ks = 0; ks < 4; ++ks) {                     \
            uint32_t pa = ((ks * 2 + khalf) ^ lmask) * 16u;                    \
            uint32_t a[4][4], b[2][4];                                         \
            _Pragma("unroll") for (int mt = 0; mt < 4; ++mt)                   \
                ldmx4(a[mt], sa + rowA[mt] + pa);                              \
            _Pragma("unroll") for (int i = 0; i < 2; ++i)                      \
                ldmx4(b[i], sb + rowB[i] + pa);                                \
            _Pragma("unroll") for (int mt = 0; mt < 4; ++mt)                   \
                _Pragma("unroll") for (int j = 0; j < 4; ++j)                  \
                    mma16816(acc[mt][j], a[mt], b[j >> 1][j & 1],              \
                             b[j >> 1][2 + (j & 1)]);                          \
        }                                                                      \
    } while (0)

    const int T = ktiles;
    LDG32(0);
    CP16T(0, 0);
    cp_commit();
    STS32(0);
    if (T > 1) LDG32(1);
    cp_wait0();
    __syncthreads();

    int s = 0;
    for (int t = 0; t < T; ++t) {
        if (t + 1 < T) { CP16T(t + 1, s ^ 1); cp_commit(); }
        COMPUTE1(s);
        if (t + 1 < T) {
            STS32(s ^ 1);
            if (t + 2 < T) LDG32(t + 2);
            cp_wait0();
        }
        __syncthreads();
        s ^= 1;
    }

    const int er = lane >> 2;
    const int ec = (lane & 3) * 2;
#pragma unroll
    for (int mt = 0; mt < 4; ++mt) {
        const int r0 = m0 + wm + mt * 16 + er;
#pragma unroll
        for (int j = 0; j < 4; ++j) {
            const int c = n0 + wn + j * 8 + ec;
            float* a = acc[mt][j];
            float s0 = g_d[c], s1 = g_d[c + 1];
            __half2 h0 = __floats2half2_rn(a[0] * s0, a[1] * s1);
            __half2 h1 = __floats2half2_rn(a[2] * s0, a[3] * s1);
            *(__half2*)(dsth + (size_t)r0 * NROWS + c) = h0;
            *(__half2*)(dsth + (size_t)(r0 + 8) * NROWS + c) = h1;
        }
    }
#undef LDG32
#undef STS32
#undef CP16T
#undef COMPUTE1
}

// ---------------------------------------------------------------------------
// GEMM2: CTA tile 128x256, 512 threads, 16 warps of 64x32, 3-stage cp.async.
// P[z][m][n] = A[m, z-slice] @ B[z-slice][n].  A fp32 (LDG->cvt->STS),
// B = g_BhT fp16 (cp.async).
// ---------------------------------------------------------------------------
__global__ __launch_bounds__(NTH2, 1)
void gemm2_hmma(const float* __restrict__ A, float* __restrict__ P) {
    extern __shared__ __align__(16) char smem_raw[];
    const uint32_t smem = cvta_smem(smem_raw);

    const int tid  = threadIdx.x;
    const int lane = tid & 31;
    const int wid  = tid >> 5;               // 0..15
    const int wm   = (wid & 1) * 64;         // 2 warps in M
    const int wn   = (wid >> 1) * 32;        // 8 warps in N

    const int m0 = blockIdx.x * BM2;
    const int kb = blockIdx.y * KLEN;

    // A loader: 4 threads/row, each 16 floats (4 x float4)
    const int arow = tid >> 2;               // 0..127
    const int aq   = tid & 3;                // quarter
    const float* gA = A + (size_t)(m0 + arow) * NROWS + kb + aq * 16;
    const uint32_t arow_off = (uint32_t)arow * 128u;
    const int armask = arow & 7;

    // B loader: 2 threads/row (256 rows), 4 x 16B chunks each
    const int brow = tid >> 1;               // 0..255
    const int bh   = tid & 1;
    const __half* gB = g_BhT + (size_t)brow * NROWS + kb + bh * 32;
    const uint32_t brow_off = 16384u + (uint32_t)brow * 128u;
    const int brmask = brow & 7;

    float4 pf[4];

#define LDGA(t)                                                                \
    do {                                                                       \
        const float4* p = (const float4*)(gA + (size_t)(t) * BK2);             \
        _Pragma("unroll") for (int j = 0; j < 4; ++j) pf[j] = __ldg(p + j);    \
    } while (0)
#define STSA(stg)                                                              \
    do {                                                                       \
        uint32_t db = smem + (stg) * STG2 + arow_off;                          \
        _Pragma("unroll") for (int c = 0; c < 2; ++c) {                        \
            __half2 h0 = __floats2half2_rn(pf[2 * c].x, pf[2 * c].y);          \
            __half2 h1 = __floats2half2_rn(pf[2 * c].z, pf[2 * c].w);          \
            __half2 h2 = __floats2half2_rn(pf[2 * c + 1].x, pf[2 * c + 1].y);  \
            __half2 h3 = __floats2half2_rn(pf[2 * c + 1].z, pf[2 * c + 1].w);  \
            uint32_t ch = (uint32_t)((aq * 2 + c) ^ armask);                   \
            sts128(db + ch * 16u, *(uint32_t*)&h0, *(uint32_t*)&h1,            \
                   *(uint32_t*)&h2, *(uint32_t*)&h3);                          \
        }                                                                      \
    } while (0)
#define CPB(stg, t)                                                            \
    do {                                                                       \
        uint32_t db = smem + (stg) * STG2 + brow_off;                          \
        const __half* p = gB + (size_t)(t) * BK2;                              \
        _Pragma("unroll") for (int j = 0; j < 4; ++j) {                        \
            uint32_t ch = (uint32_t)((bh * 4 + j) ^ brmask);                   \
            cp16(db + ch * 16u, p + j * 8);                                    \
        }                                                                      \
    } while (0)

    float acc[4][4][4];
#pragma unroll
    for (int i = 0; i < 4; ++i)
#pragma unroll
        for (int j = 0; j < 4; ++j)
#pragma unroll
            for (int q = 0; q < 4; ++q) acc[i][j][q] = 0.0f;

    const int lr8 = (lane & 7) + ((lane >> 3) & 1) * 8;
    uint32_t rowA[4], rowB[2];
#pragma unroll
    for (int mt = 0; mt < 4; ++mt) rowA[mt] = (uint32_t)(wm + mt * 16 + lr8) * 128u;
#pragma unroll
    for (int i = 0; i < 2; ++i)
        rowB[i] = 16384u + (uint32_t)(wn + i * 16 + lr8) * 128u;
    const uint32_t lmask = (uint32_t)(lane & 7);
    const uint32_t khalf = (uint32_t)(lane >> 4);

#define COMPUTE2(stg)                                                          \
    do {                                                                       \
        uint32_t sb0 = smem + (stg) * STG2;                                    \
        _Pragma("unroll") for (int ks = 0; ks < 4; ++ks) {                     \
            uint32_t pa = ((ks * 2 + khalf) ^ lmask) * 16u;                    \
            uint32_t a[4][4], b[2][4];                                         \
            _Pragma("unroll") for (int mt = 0; mt < 4; ++mt)                   \
                ldmx4(a[mt], sb0 + rowA[mt] + pa);                             \
            _Pragma("unroll") for (int i = 0; i < 2; ++i)                      \
                ldmx4(b[i], sb0 + rowB[i] + pa);                               \
            _Pragma("unroll") for (int mt = 0; mt < 4; ++mt)                   \
                _Pragma("unroll") for (int j = 0; j < 4; ++j)                  \
                    mma16816(acc[mt][j], a[mt], b[j >> 1][j & 1],              \
                             b[j >> 1][2 + (j & 1)]);                          \
        }                                                                      \
    } while (0)

    const int T = KLEN / BK2;  // 64

    // prologue
    LDGA(0);
    CPB(0, 0); cp_commit();
    STSA(0);
    LDGA(1);
    CPB(1, 1); cp_commit();
    STSA(1);
    LDGA(2);

    int s = 0;
    for (int t = 0; t < T; ++t) {
        cp_wait1();
        __syncthreads();
        const int ts = t + 2;
        if (ts < T) {
            const int stg = (s + 2 >= NSTG) ? (s + 2 - NSTG) : (s + 2);
            STSA(stg);                        // pf holds tile ts
            if (t + 3 < T) LDGA(t + 3);
            CPB(stg, ts);
        }
        cp_commit();
        COMPUTE2(s);
        s = (s + 1 == NSTG) ? 0 : (s + 1);
    }

    // epilogue -> fp32 partials
    float* Pz = P + (size_t)blockIdx.y * NROWS * NCH;
    const int er = lane >> 2;
    const int ec = (lane & 3) * 2;
#pragma unroll
    for (int mt = 0; mt < 4; ++mt) {
        const int r0 = m0 + wm + mt * 16 + er;
#pragma unroll
        for (int j = 0; j < 4; ++j) {
            const int c = wn + j * 8 + ec;
            float* a = acc[mt][j];
            *(float2*)(Pz + (size_t)r0 * NCH + c) = make_float2(a[0], a[1]);
            *(float2*)(Pz + (size_t)(r0 + 8) * NCH + c) = make_float2(a[2], a[3]);
        }
    }
#undef LDGA
#undef STSA
#undef CPB
#undef COMPUTE2
}

// ---------------- launch ----------------
extern "C" void kernel_launch(void* const* d_in, const int* in_sizes, int n_in,
                              void* d_out, int out_size) {
    (void)in_sizes; (void)n_in; (void)out_size;
    const float* A = (const float*)d_in[0];
    const float* D = (const float*)d_in[1];
    const float* H = (const float*)d_in[2];
    const float* W = (const float*)d_in[3];
    float* out = (float*)d_out;

    __half *pWhT, *pBhT;
    float* pP;
    cudaGetSymbolAddress((void**)&pWhT, g_WhT);
    cudaGetSymbolAddress((void**)&pBhT, g_BhT);
    cudaGetSymbolAddress((void**)&pP, g_P);

    cudaFuncSetAttribute(gemm1_hmma, cudaFuncAttributeMaxDynamicSharedMemorySize,
                         SMEM_SZ);
    cudaFuncSetAttribute(gemm2_hmma, cudaFuncAttributeMaxDynamicSharedMemorySize,
                         SMEM2);

    compute_d_kernel<<<NROWS / 256, 256>>>(D);
    convW_kernel<<<NCH, NCH>>>(W);

    // BhT[n][m] = d[m] * (W^T @ H^T)[n][m]
    gemm1_hmma<<<dim3(NROWS / BN, NCH / BM), NTHREADS, SMEM_SZ>>>(
        H, NCH, pWhT, NCH, NCH / BK, pBhT);

    // P[z] = A[:, z-slice] @ B[z-slice, :]
    gemm2_hmma<<<dim3(NROWS / BM2, KSPLIT), NTH2, SMEM2>>>(A, pP);

    // out = diag(d) * (P0 + P1)
    reduce_kernel<<<(NROWS * NCH) / 1024, 256>>>(out);
}

// round 7
// speedup vs baseline: 5.6094x; 1.0004x over previous
#include <cuda_runtime.h>
#include <cuda_fp16.h>
#include <cstdint>

#define NROWS 8192
#define NCH   256

// ---- GEMM1 (small) tiling ----
#define BM 128
#define BN 128
#define BK 64
#define NTHREADS 256
#define STAGE_BYTES 32768
#define SMEM_SZ (2 * STAGE_BYTES)

// ---- GEMM2 (big) tiling ----
#define BM2 128
#define BN2 256
#define BK2 64
#define NTH2 512
#define KSPLIT 2
#define KLEN (NROWS / KSPLIT)      // 4096
#define NSTG 4
#define STG2 49152                 // A 16KB + B 32KB
#define SMEM2 (NSTG * STG2)        // 196608

// ---------------- device scratch ----------------
__device__ float  g_d[NROWS];
__device__ __half g_WhT[NCH * NCH];            // W^T fp16 [n][k]
__device__ __half g_BhT[(size_t)NCH * NROWS];  // B^T fp16 [n][m]
__device__ float  g_P[(size_t)KSPLIT * NROWS * NCH];

// ---------------- PTX helpers ----------------
__device__ __forceinline__ uint32_t cvta_smem(const void* p) {
    uint32_t a;
    asm("{ .reg .u64 t; cvta.to.shared.u64 t, %1; cvt.u32.u64 %0, t; }"
        : "=r"(a) : "l"(p));
    return a;
}
__device__ __forceinline__ void cp16(uint32_t saddr, const void* gaddr) {
    asm volatile("cp.async.cg.shared.global [%0], [%1], 16;"
                 :: "r"(saddr), "l"(gaddr) : "memory");
}
__device__ __forceinline__ void cp_commit() {
    asm volatile("cp.async.commit_group;" ::: "memory");
}
__device__ __forceinline__ void cp_wait0() {
    asm volatile("cp.async.wait_group 0;" ::: "memory");
}
__device__ __forceinline__ void cp_wait2() {
    asm volatile("cp.async.wait_group 2;" ::: "memory");
}
__device__ __forceinline__ void ldmx4(uint32_t* r, uint32_t addr) {
    asm volatile("ldmatrix.sync.aligned.m8n8.x4.shared.b16 {%0,%1,%2,%3}, [%4];"
                 : "=r"(r[0]), "=r"(r[1]), "=r"(r[2]), "=r"(r[3]) : "r"(addr));
}
__device__ __forceinline__ void mma16816(float* c, const uint32_t* a,
                                         uint32_t b0, uint32_t b1) {
    asm volatile(
        "mma.sync.aligned.m16n8k16.row.col.f32.f16.f16.f32 "
        "{%0,%1,%2,%3}, {%4,%5,%6,%7}, {%8,%9}, {%0,%1,%2,%3};"
        : "+f"(c[0]), "+f"(c[1]), "+f"(c[2]), "+f"(c[3])
        : "r"(a[0]), "r"(a[1]), "r"(a[2]), "r"(a[3]), "r"(b0), "r"(b1));
}
__device__ __forceinline__ void sts128(uint32_t addr, uint32_t x, uint32_t y,
                                       uint32_t z, uint32_t w) {
    asm volatile("st.shared.v4.b32 [%0], {%1,%2,%3,%4};"
                 :: "r"(addr), "r"(x), "r"(y), "r"(z), "r"(w) : "memory");
}

// ---------------- small kernels ----------------
__global__ void compute_d_kernel(const float* __restrict__ D) {
    int i = blockIdx.x * blockDim.x + threadIdx.x;
    float x = D[(size_t)i * (NROWS + 1)];
    float r = rsqrtf(x);
    r = r * (1.5f - 0.5f * x * r * r);
    g_d[i] = r;
}
__global__ void convW_kernel(const float* __restrict__ W) {
    int k = blockIdx.x, n = threadIdx.x;
    g_WhT[n * NCH + k] = __float2half_rn(W[k * NCH + n]);
}
// out[m][n] = d[m] * (P0[m][n] + P1[m][n])
__global__ void reduce_kernel(float* __restrict__ out) {
    size_t base = ((size_t)blockIdx.x * blockDim.x + threadIdx.x) * 4;
    int row = (int)(base >> 8);
    float sc = g_d[row];
    float4 a = *(const float4*)(g_P + base);
    float4 b = *(const float4*)(g_P + (size_t)NROWS * NCH + base);
    float4 o;
    o.x = sc * (a.x + b.x);
    o.y = sc * (a.y + b.y);
    o.z = sc * (a.z + b.z);
    o.w = sc * (a.w + b.w);
    *(float4*)(out + base) = o;
}

// ---------------------------------------------------------------------------
// GEMM1 (2-stage): BhT[n][m] = d[m] * (W^T @ H^T)[n][m], fp16 out.
// ---------------------------------------------------------------------------
__global__ __launch_bounds__(NTHREADS, 1)
void gemm1_hmma(const float* __restrict__ f32op, int ld32,
                const __half* __restrict__ f16op, int ld16,
                int ktiles, __half* __restrict__ dsth) {
    extern __shared__ __align__(16) char smem_raw[];
    const uint32_t smem = cvta_smem(smem_raw);

    const int tid  = threadIdx.x;
    const int lane = tid & 31;
    const int wid  = tid >> 5;
    const int wm   = (wid & 1) * 64;
    const int wn   = (wid >> 1) * 32;

    const int m0 = blockIdx.y * BM;   // n-channel dim
    const int n0 = blockIdx.x * BN;   // node dim

    const uint32_t off32 = 16384u;
    const uint32_t off16 = 0u;

    const int lrow = tid >> 1;
    const int lseg = tid & 1;
    const float* g32 = f32op + (size_t)(n0 + lrow) * ld32 + lseg * 32;
    const __half* g16 = f16op + (size_t)(m0 + lrow) * ld16 + lseg * 32;
    const uint32_t srow = (uint32_t)lrow * 128u;
    const int rmask = lrow & 7;

    float4 pf[8];

#define LDG32(t)                                                               \
    do {                                                                       \
        const float4* p = (const float4*)(g32 + (size_t)(t) * BK);             \
        _Pragma("unroll") for (int j = 0; j < 8; ++j) pf[j] = __ldg(p + j);    \
    } while (0)
#define STS32(stg)                                                             \
    do {                                                                       \
        uint32_t db = smem + (stg) * STAGE_BYTES + off32 + srow;               \
        _Pragma("unroll") for (int c = 0; c < 4; ++c) {                        \
            __half2 h0 = __floats2half2_rn(pf[2 * c].x, pf[2 * c].y);          \
            __half2 h1 = __floats2half2_rn(pf[2 * c].z, pf[2 * c].w);          \
            __half2 h2 = __floats2half2_rn(pf[2 * c + 1].x, pf[2 * c + 1].y);  \
            __half2 h3 = __floats2half2_rn(pf[2 * c + 1].z, pf[2 * c + 1].w);  \
            uint32_t ch = (uint32_t)((lseg * 4 + c) ^ rmask);                  \
            sts128(db + ch * 16u, *(uint32_t*)&h0, *(uint32_t*)&h1,            \
                   *(uint32_t*)&h2, *(uint32_t*)&h3);                          \
        }                                                                      \
    } while (0)
#define CP16T(t, stg)                                                          \
    do {                                                                       \
        uint32_t db = smem + (stg) * STAGE_BYTES + off16 + srow;               \
        const __half* p = g16 + (size_t)(t) * BK;                              \
        _Pragma("unroll") for (int j = 0; j < 4; ++j) {                        \
            uint32_t ch = (uint32_t)((lseg * 4 + j) ^ rmask);                  \
            cp16(db + ch * 16u, p + j * 8);                                    \
        }                                                                      \
    } while (0)

    float acc[4][4][4];
#pragma unroll
    for (int i = 0; i < 4; ++i)
#pragma unroll
        for (int j = 0; j < 4; ++j)
#pragma unroll
            for (int q = 0; q < 4; ++q) acc[i][j][q] = 0.0f;

    const int lr8 = (lane & 7) + ((lane >> 3) & 1) * 8;
    uint32_t rowA[4], rowB[2];
#pragma unroll
    for (int mt = 0; mt < 4; ++mt) rowA[mt] = (uint32_t)(wm + mt * 16 + lr8) * 128u;
#pragma unroll
    for (int i = 0; i < 2; ++i) rowB[i] = (uint32_t)(wn + i * 16 + lr8) * 128u;
    const uint32_t lmask = (uint32_t)(lane & 7);
    const uint32_t khalf = (uint32_t)(lane >> 4);

#define COMPUTE1(stg)                                                          \
    do {                                                                       \
        uint32_t sa = smem + (stg) * STAGE_BYTES + off16;                      \
        uint32_t sb = smem + (stg) * STAGE_BYTES + off32;                      \
        _Pragma("unroll") for (int ks = 0; ks < 4; ++ks) {                     \
            uint32_t pa = ((ks * 2 + khalf) ^ lmask) * 16u;                    \
            uint32_t a[4][4], b[2][4];                                         \
            _Pragma("unroll") for (int mt = 0; mt < 4; ++mt)                   \
                ldmx4(a[mt], sa + rowA[mt] + pa);                              \
            _Pragma("unroll") for (int i = 0; i < 2; ++i)                      \
                ldmx4(b[i], sb + rowB[i] + pa);                                \
            _Pragma("unroll") for (int mt = 0; mt < 4; ++mt)                   \
                _Pragma("unroll") for (int j = 0; j < 4; ++j)                  \
                    mma16816(acc[mt][j], a[mt], b[j >> 1][j & 1],              \
                             b[j >> 1][2 + (j & 1)]);                          \
        }                                                                      \
    } while (0)

    const int T = ktiles;
    LDG32(0);
    CP16T(0, 0);
    cp_commit();
    STS32(0);
    if (T > 1) LDG32(1);
    cp_wait0();
    __syncthreads();

    int s = 0;
    for (int t = 0; t < T; ++t) {
        if (t + 1 < T) { CP16T(t + 1, s ^ 1); cp_commit(); }
        COMPUTE1(s);
        if (t + 1 < T) {
            STS32(s ^ 1);
            if (t + 2 < T) LDG32(t + 2);
            cp_wait0();
        }
        __syncthreads();
        s ^= 1;
    }

    const int er = lane >> 2;
    const int ec = (lane & 3) * 2;
#pragma unroll
    for (int mt = 0; mt < 4; ++mt) {
        const int r0 = m0 + wm + mt * 16 + er;
#pragma unroll
        for (int j = 0; j < 4; ++j) {
            const int c = n0 + wn + j * 8 + ec;
            float* a = acc[mt][j];
            float s0 = g_d[c], s1 = g_d[c + 1];
            __half2 h0 = __floats2half2_rn(a[0] * s0, a[1] * s1);
            __half2 h1 = __floats2half2_rn(a[2] * s0, a[3] * s1);
            *(__half2*)(dsth + (size_t)r0 * NROWS + c) = h0;
            *(__half2*)(dsth + (size_t)(r0 + 8) * NROWS + c) = h1;
        }
    }
#undef LDG32
#undef STS32
#undef CP16T
#undef COMPUTE1
}

// ---------------------------------------------------------------------------
// GEMM2: CTA 128x256, 512 threads, 16 warps of 64x32, 4-stage cp.async,
// prefetch distance 3, A-fragment software pipelining inside the k-slab.
// ---------------------------------------------------------------------------
__global__ __launch_bounds__(NTH2, 1)
void gemm2_hmma(const float* __restrict__ A, float* __restrict__ P) {
    extern __shared__ __align__(16) char smem_raw[];
    const uint32_t smem = cvta_smem(smem_raw);

    const int tid  = threadIdx.x;
    const int lane = tid & 31;
    const int wid  = tid >> 5;               // 0..15
    const int wm   = (wid & 1) * 64;         // 2 warps in M
    const int wn   = (wid >> 1) * 32;        // 8 warps in N

    const int m0 = blockIdx.x * BM2;
    const int kb = blockIdx.y * KLEN;

    // A loader: 4 threads/row, each 16 floats (4 x float4)
    const int arow = tid >> 2;               // 0..127
    const int aq   = tid & 3;                // quarter
    const float* gA = A + (size_t)(m0 + arow) * NROWS + kb + aq * 16;
    const uint32_t arow_off = (uint32_t)arow * 128u;
    const int armask = arow & 7;

    // B loader: 2 threads/row (256 rows), 4 x 16B chunks each
    const int brow = tid >> 1;               // 0..255
    const int bh   = tid & 1;
    const __half* gB = g_BhT + (size_t)brow * NROWS + kb + bh * 32;
    const uint32_t brow_off = 16384u + (uint32_t)brow * 128u;
    const int brmask = brow & 7;

    float4 pf[4];

#define LDGA(t)                                                                \
    do {                                                                       \
        const float4* p = (const float4*)(gA + (size_t)(t) * BK2);             \
        _Pragma("unroll") for (int j = 0; j < 4; ++j) pf[j] = __ldg(p + j);    \
    } while (0)
#define STSA(stg)                                                              \
    do {                                                                       \
        uint32_t db = smem + (stg) * STG2 + arow_off;                          \
        _Pragma("unroll") for (int c = 0; c < 2; ++c) {                        \
            __half2 h0 = __floats2half2_rn(pf[2 * c].x, pf[2 * c].y);          \
            __half2 h1 = __floats2half2_rn(pf[2 * c].z, pf[2 * c].w);          \
            __half2 h2 = __floats2half2_rn(pf[2 * c + 1].x, pf[2 * c + 1].y);  \
            __half2 h3 = __floats2half2_rn(pf[2 * c + 1].z, pf[2 * c + 1].w);  \
            uint32_t ch = (uint32_t)((aq * 2 + c) ^ armask);                   \
            sts128(db + ch * 16u, *(uint32_t*)&h0, *(uint32_t*)&h1,            \
                   *(uint32_t*)&h2, *(uint32_t*)&h3);                          \
        }                                                                      \
    } while (0)
#define CPB(stg, t)                                                            \
    do {                                                                       \
        uint32_t db = smem + (stg) * STG2 + brow_off;                          \
        const __half* p = gB + (size_t)(t) * BK2;                              \
        _Pragma("unroll") for (int j = 0; j < 4; ++j) {                        \
            uint32_t ch = (uint32_t)((bh * 4 + j) ^ brmask);                   \
            cp16(db + ch * 16u, p + j * 8);                                    \
        }                                                                      \
    } while (0)

    float acc[4][4][4];
#pragma unroll
    for (int i = 0; i < 4; ++i)
#pragma unroll
        for (int j = 0; j < 4; ++j)
#pragma unroll
            for (int q = 0; q < 4; ++q) acc[i][j][q] = 0.0f;

    const int lr8 = (lane & 7) + ((lane >> 3) & 1) * 8;
    uint32_t rowA[4], rowB[2];
#pragma unroll
    for (int mt = 0; mt < 4; ++mt) rowA[mt] = (uint32_t)(wm + mt * 16 + lr8) * 128u;
#pragma unroll
    for (int i = 0; i < 2; ++i)
        rowB[i] = 16384u + (uint32_t)(wn + i * 16 + lr8) * 128u;
    const uint32_t lmask = (uint32_t)(lane & 7);
    const uint32_t khalf = (uint32_t)(lane >> 4);

    // A-frag double-buffered compute: loads for ks+1 overlap HMMA of ks.
#define COMPUTE2(stg)                                                          \
    do {                                                                       \
        uint32_t sb0 = smem + (stg) * STG2;                                    \
        uint32_t afr[2][4][4], bfr[2][4];                                      \
        {                                                                      \
            uint32_t pa0 = (khalf ^ lmask) * 16u;                              \
            _Pragma("unroll") for (int mt = 0; mt < 4; ++mt)                   \
                ldmx4(afr[0][mt], sb0 + rowA[mt] + pa0);                       \
        }                                                                      \
        _Pragma("unroll") for (int ks = 0; ks < 4; ++ks) {                     \
            uint32_t pb = ((ks * 2 + khalf) ^ lmask) * 16u;                    \
            ldmx4(bfr[0], sb0 + rowB[0] + pb);                                 \
            ldmx4(bfr[1], sb0 + rowB[1] + pb);                                 \
            if (ks < 3) {                                                      \
                uint32_t pn = (((ks + 1) * 2 + khalf) ^ lmask) * 16u;          \
                _Pragma("unroll") for (int mt = 0; mt < 4; ++mt)               \
                    ldmx4(afr[(ks + 1) & 1][mt], sb0 + rowA[mt] + pn);         \
            }                                                                  \
            _Pragma("unroll") for (int mt = 0; mt < 4; ++mt)                   \
                _Pragma("unroll") for (int j = 0; j < 4; ++j)                  \
                    mma16816(acc[mt][j], afr[ks & 1][mt],                      \
                             bfr[j >> 1][j & 1], bfr[j >> 1][2 + (j & 1)]);    \
        }                                                                      \
    } while (0)

    const int T = KLEN / BK2;  // 64

    // prologue: 3 tiles staged, A of tile 3 in regs
    LDGA(0); CPB(0, 0); cp_commit(); STSA(0);
    LDGA(1); CPB(1, 1); cp_commit(); STSA(1);
    LDGA(2); CPB(2, 2); cp_commit(); STSA(2);
    LDGA(3);

    int s = 0;
    for (int t = 0; t < T; ++t) {
        cp_wait2();
        __syncthreads();
        const int ts = t + 3;
        if (ts < T) {
            const int stg = (s + 3 >= NSTG) ? (s + 3 - NSTG) : (s + 3);
            STSA(stg);                        // pf holds tile ts
            if (t + 4 < T) LDGA(t + 4);
            CPB(stg, ts);
        }
        cp_commit();
        COMPUTE2(s);
        s = (s + 1 == NSTG) ? 0 : (s + 1);
    }

    // epilogue -> fp32 partials
    float* Pz = P + (size_t)blockIdx.y * NROWS * NCH;
    const int er = lane >> 2;
    const int ec = (lane & 3) * 2;
#pragma unroll
    for (int mt = 0; mt < 4; ++mt) {
        const int r0 = m0 + wm + mt * 16 + er;
#pragma unroll
        for (int j = 0; j < 4; ++j) {
            const int c = wn + j * 8 + ec;
            float* a = acc[mt][j];
            *(float2*)(Pz + (size_t)r0 * NCH + c) = make_float2(a[0], a[1]);
            *(float2*)(Pz + (size_t)(r0 + 8) * NCH + c) = make_float2(a[2], a[3]);
        }
    }
#undef LDGA
#undef STSA
#undef CPB
#undef COMPUTE2
}

// ---------------- launch ----------------
extern "C" void kernel_launch(void* const* d_in, const int* in_sizes, int n_in,
                              void* d_out, int out_size) {
    (void)in_sizes; (void)n_in; (void)out_size;
    const float* A = (const float*)d_in[0];
    const float* D = (const float*)d_in[1];
    const float* H = (const float*)d_in[2];
    const float* W = (const float*)d_in[3];
    float* out = (float*)d_out;

    __half *pWhT, *pBhT;
    float* pP;
    cudaGetSymbolAddress((void**)&pWhT, g_WhT);
    cudaGetSymbolAddress((void**)&pBhT, g_BhT);
    cudaGetSymbolAddress((void**)&pP, g_P);

    cudaFuncSetAttribute(gemm1_hmma, cudaFuncAttributeMaxDynamicSharedMemorySize,
                         SMEM_SZ);
    cudaFuncSetAttribute(gemm2_hmma, cudaFuncAttributeMaxDynamicSharedMemorySize,
                         SMEM2);

    compute_d_kernel<<<NROWS / 256, 256>>>(D);
    convW_kernel<<<NCH, NCH>>>(W);

    // BhT[n][m] = d[m] * (W^T @ H^T)[n][m]
    gemm1_hmma<<<dim3(NROWS / BN, NCH / BM), NTHREADS, SMEM_SZ>>>(
        H, NCH, pWhT, NCH, NCH / BK, pBhT);

    // P[z] = A[:, z-slice] @ B[z-slice, :]
    gemm2_hmma<<<dim3(NROWS / BM2, KSPLIT), NTH2, SMEM2>>>(A, pP);

    // out = diag(d) * (P0 + P1)
    reduce_kernel<<<(NROWS * NCH) / 1024, 256>>>(out);
}

// round 8
// speedup vs baseline: 7.0060x; 1.2490x over previous
#include <cuda_runtime.h>
#include <cuda_fp16.h>
#include <cstdint>

#define NROWS 8192
#define NCH   256

// ---- GEMM1 (small) tiling ----
#define BM 128
#define BN 128
#define BK 64
#define NTHREADS 256
#define STAGE_BYTES 32768
#define SMEM_SZ (2 * STAGE_BYTES)

// ---- GEMM2 (big) tiling ----
#define BM2 128
#define BN2 256
#define BK2 64
#define NTH2 512
#define KSPLIT 2
#define KLEN (NROWS / KSPLIT)      // 4096
#define NSTG 4
#define STG2 49152                 // A 16KB + B 32KB
#define SMEM2 (NSTG * STG2 + 128)  // stages + mbarriers

// ---------------- device scratch ----------------
__device__ float  g_d[NROWS];
__device__ __half g_WhT[NCH * NCH];            // W^T fp16 [n][k]
__device__ __half g_BhT[(size_t)NCH * NROWS];  // B^T fp16 [n][m]
__device__ float  g_P[(size_t)KSPLIT * NROWS * NCH];

// ---------------- PTX helpers ----------------
__device__ __forceinline__ uint32_t cvta_smem(const void* p) {
    uint32_t a;
    asm("{ .reg .u64 t; cvta.to.shared.u64 t, %1; cvt.u32.u64 %0, t; }"
        : "=r"(a) : "l"(p));
    return a;
}
__device__ __forceinline__ uint32_t elect_one() {
    uint32_t r;
    asm volatile("{ .reg .pred p; elect.sync _|p, 0xFFFFFFFF; selp.b32 %0,1,0,p; }"
                 : "=r"(r));
    return r;
}
__device__ __forceinline__ void cp16(uint32_t saddr, const void* gaddr) {
    asm volatile("cp.async.cg.shared.global [%0], [%1], 16;"
                 :: "r"(saddr), "l"(gaddr) : "memory");
}
__device__ __forceinline__ void cp_commit() {
    asm volatile("cp.async.commit_group;" ::: "memory");
}
__device__ __forceinline__ void cp_wait0() {
    asm volatile("cp.async.wait_group 0;" ::: "memory");
}
__device__ __forceinline__ void cp_wait1() {
    asm volatile("cp.async.wait_group 1;" ::: "memory");
}
__device__ __forceinline__ void mbar_init(uint32_t m, uint32_t cnt) {
    asm volatile("mbarrier.init.shared.b64 [%0], %1;" :: "r"(m), "r"(cnt) : "memory");
}
__device__ __forceinline__ void mbar_arrive(uint32_t m) {
    asm volatile("{ .reg .b64 st; mbarrier.arrive.shared.b64 st, [%0]; }"
                 :: "r"(m) : "memory");
}
__device__ __forceinline__ void mbar_wait(uint32_t m, uint32_t parity) {
    asm volatile(
        "{\n\t.reg .pred P;\n"
        "LW_%=:\n\t"
        "mbarrier.try_wait.parity.acquire.cta.shared::cta.b64 P, [%0], %1, 0x989680;\n\t"
        "@P bra.uni LD_%=;\n\t"
        "bra.uni LW_%=;\n"
        "LD_%=:\n\t}"
        :: "r"(m), "r"(parity) : "memory");
}
__device__ __forceinline__ void ldmx4(uint32_t* r, uint32_t addr) {
    asm volatile("ldmatrix.sync.aligned.m8n8.x4.shared.b16 {%0,%1,%2,%3}, [%4];"
                 : "=r"(r[0]), "=r"(r[1]), "=r"(r[2]), "=r"(r[3]) : "r"(addr));
}
__device__ __forceinline__ void mma16816(float* c, const uint32_t* a,
                                         uint32_t b0, uint32_t b1) {
    asm volatile(
        "mma.sync.aligned.m16n8k16.row.col.f32.f16.f16.f32 "
        "{%0,%1,%2,%3}, {%4,%5,%6,%7}, {%8,%9}, {%0,%1,%2,%3};"
        : "+f"(c[0]), "+f"(c[1]), "+f"(c[2]), "+f"(c[3])
        : "r"(a[0]), "r"(a[1]), "r"(a[2]), "r"(a[3]), "r"(b0), "r"(b1));
}
__device__ __forceinline__ void sts128(uint32_t addr, uint32_t x, uint32_t y,
                                       uint32_t z, uint32_t w) {
    asm volatile("st.shared.v4.b32 [%0], {%1,%2,%3,%4};"
                 :: "r"(addr), "r"(x), "r"(y), "r"(z), "r"(w) : "memory");
}

// ---------------- small kernels ----------------
__global__ void compute_d_kernel(const float* __restrict__ D) {
    int i = blockIdx.x * blockDim.x + threadIdx.x;
    float x = D[(size_t)i * (NROWS + 1)];
    float r = rsqrtf(x);
    r = r * (1.5f - 0.5f * x * r * r);
    g_d[i] = r;
}
__global__ void convW_kernel(const float* __restrict__ W) {
    int k = blockIdx.x, n = threadIdx.x;
    g_WhT[n * NCH + k] = __float2half_rn(W[k * NCH + n]);
}
// out[m][n] = d[m] * (P0[m][n] + P1[m][n])
__global__ void reduce_kernel(float* __restrict__ out) {
    size_t base = ((size_t)blockIdx.x * blockDim.x + threadIdx.x) * 4;
    int row = (int)(base >> 8);
    float sc = g_d[row];
    float4 a = *(const float4*)(g_P + base);
    float4 b = *(const float4*)(g_P + (size_t)NROWS * NCH + base);
    float4 o;
    o.x = sc * (a.x + b.x);
    o.y = sc * (a.y + b.y);
    o.z = sc * (a.z + b.z);
    o.w = sc * (a.w + b.w);
    *(float4*)(out + base) = o;
}

// ---------------------------------------------------------------------------
// GEMM1 (2-stage lockstep, unchanged): BhT[n][m] = d[m]*(W^T @ H^T)[n][m]
// ---------------------------------------------------------------------------
__global__ __launch_bounds__(NTHREADS, 1)
void gemm1_hmma(const float* __restrict__ f32op, int ld32,
                const __half* __restrict__ f16op, int ld16,
                int ktiles, __half* __restrict__ dsth) {
    extern __shared__ __align__(16) char smem_raw[];
    const uint32_t smem = cvta_smem(smem_raw);

    const int tid  = threadIdx.x;
    const int lane = tid & 31;
    const int wid  = tid >> 5;
    const int wm   = (wid & 1) * 64;
    const int wn   = (wid >> 1) * 32;

    const int m0 = blockIdx.y * BM;   // n-channel dim
    const int n0 = blockIdx.x * BN;   // node dim

    const uint32_t off32 = 16384u;
    const uint32_t off16 = 0u;

    const int lrow = tid >> 1;
    const int lseg = tid & 1;
    const float* g32 = f32op + (size_t)(n0 + lrow) * ld32 + lseg * 32;
    const __half* g16 = f16op + (size_t)(m0 + lrow) * ld16 + lseg * 32;
    const uint32_t srow = (uint32_t)lrow * 128u;
    const int rmask = lrow & 7;

    float4 pf[8];

#define LDG32(t)                                                               \
    do {                                                                       \
        const float4* p = (const float4*)(g32 + (size_t)(t) * BK);             \
        _Pragma("unroll") for (int j = 0; j < 8; ++j) pf[j] = __ldg(p + j);    \
    } while (0)
#define STS32(stg)                                                             \
    do {                                                                       \
        uint32_t db = smem + (stg) * STAGE_BYTES + off32 + srow;               \
        _Pragma("unroll") for (int c = 0; c < 4; ++c) {                        \
            __half2 h0 = __floats2half2_rn(pf[2 * c].x, pf[2 * c].y);          \
            __half2 h1 = __floats2half2_rn(pf[2 * c].z, pf[2 * c].w);          \
            __half2 h2 = __floats2half2_rn(pf[2 * c + 1].x, pf[2 * c + 1].y);  \
            __half2 h3 = __floats2half2_rn(pf[2 * c + 1].z, pf[2 * c + 1].w);  \
            uint32_t ch = (uint32_t)((lseg * 4 + c) ^ rmask);                  \
            sts128(db + ch * 16u, *(uint32_t*)&h0, *(uint32_t*)&h1,            \
                   *(uint32_t*)&h2, *(uint32_t*)&h3);                          \
        }                                                                      \
    } while (0)
#define CP16T(t, stg)                                                          \
    do {                                                                       \
        uint32_t db = smem + (stg) * STAGE_BYTES + off16 + srow;               \
        const __half* p = g16 + (size_t)(t) * BK;                              \
        _Pragma("unroll") for (int j = 0; j < 4; ++j) {                        \
            uint32_t ch = (uint32_t)((lseg * 4 + j) ^ rmask);                  \
            cp16(db + ch * 16u, p + j * 8);                                    \
        }                                                                      \
    } while (0)

    float acc[4][4][4];
#pragma unroll
    for (int i = 0; i < 4; ++i)
#pragma unroll
        for (int j = 0; j < 4; ++j)
#pragma unroll
            for (int q = 0; q < 4; ++q) acc[i][j][q] = 0.0f;

    const int lr8 = (lane & 7) + ((lane >> 3) & 1) * 8;
    uint32_t rowA[4], rowB[2];
#pragma unroll
    for (int mt = 0; mt < 4; ++mt) rowA[mt] = (uint32_t)(wm + mt * 16 + lr8) * 128u;
#pragma unroll
    for (int i = 0; i < 2; ++i) rowB[i] = (uint32_t)(wn + i * 16 + lr8) * 128u;
    const uint32_t lmask = (uint32_t)(lane & 7);
    const uint32_t khalf = (uint32_t)(lane >> 4);

#define COMPUTE1(stg)                                                          \
    do {                                                                       \
        uint32_t sa = smem + (stg) * STAGE_BYTES + off16;                      \
        uint32_t sb = smem + (stg) * STAGE_BYTES + off32;                      \
        _Pragma("unroll") for (int ks = 0; ks < 4; ++ks) {                     \
            uint32_t pa = ((ks * 2 + khalf) ^ lmask) * 16u;                    \
            uint32_t a[4][4], b[2][4];                                         \
            _Pragma("unroll") for (int mt = 0; mt < 4; ++mt)                   \
                ldmx4(a[mt], sa + rowA[mt] + pa);                              \
            _Pragma("unroll") for (int i = 0; i < 2; ++i)                      \
                ldmx4(b[i], sb + rowB[i] + pa);                                \
            _Pragma("unroll") for (int mt = 0; mt < 4; ++mt)                   \
                _Pragma("unroll") for (int j = 0; j < 4; ++j)                  \
                    mma16816(acc[mt][j], a[mt], b[j >> 1][j & 1],              \
                             b[j >> 1][2 + (j & 1)]);                          \
        }                                                                      \
    } while (0)

    const int T = ktiles;
    LDG32(0);
    CP16T(0, 0);
    cp_commit();
    STS32(0);
    if (T > 1) LDG32(1);
    cp_wait0();
    __syncthreads();

    int s = 0;
    for (int t = 0; t < T; ++t) {
        if (t + 1 < T) { CP16T(t + 1, s ^ 1); cp_commit(); }
        COMPUTE1(s);
        if (t + 1 < T) {
            STS32(s ^ 1);
            if (t + 2 < T) LDG32(t + 2);
            cp_wait0();
        }
        __syncthreads();
        s ^= 1;
    }

    const int er = lane >> 2;
    const int ec = (lane & 3) * 2;
#pragma unroll
    for (int mt = 0; mt < 4; ++mt) {
        const int r0 = m0 + wm + mt * 16 + er;
#pragma unroll
        for (int j = 0; j < 4; ++j) {
            const int c = n0 + wn + j * 8 + ec;
            float* a = acc[mt][j];
            float s0 = g_d[c], s1 = g_d[c + 1];
            __half2 h0 = __floats2half2_rn(a[0] * s0, a[1] * s1);
            __half2 h1 = __floats2half2_rn(a[2] * s0, a[3] * s1);
            *(__half2*)(dsth + (size_t)r0 * NROWS + c) = h0;
            *(__half2*)(dsth + (size_t)(r0 + 8) * NROWS + c) = h1;
        }
    }
#undef LDG32
#undef STS32
#undef CP16T
#undef COMPUTE1
}

// ---------------------------------------------------------------------------
// GEMM2: CTA 128x256, 512 threads, 16 warps of 64x32, 4-stage pipeline with
// per-stage full/empty mbarriers (NO __syncthreads in the mainloop).
// Fill distance 3: iteration t computes tile t (stage t&3) and fills tile
// t+3 (stage (t+3)&3). A fill is published (full arrive) one iteration later,
// after the thread's own cp.asyncs drained (cp_wait1) — covers STS + cp data.
// Warps free-run, bounded by stage buffers instead of a CTA barrier.
// ---------------------------------------------------------------------------
__global__ __launch_bounds__(NTH2, 1)
void gemm2_hmma(const float* __restrict__ A, float* __restrict__ P) {
    extern __shared__ __align__(16) char smem_raw[];
    const uint32_t smem = cvta_smem(smem_raw);
    const uint32_t mb = smem + NSTG * STG2;   // full[s]=mb+16s, empty[s]=+16s+8

    const int tid  = threadIdx.x;
    const int lane = tid & 31;
    const int wid  = tid >> 5;               // 0..15
    const int wm   = (wid & 1) * 64;         // 2 warps in M
    const int wn   = (wid >> 1) * 32;        // 8 warps in N

    const int m0 = blockIdx.x * BM2;
    const int kb = blockIdx.y * KLEN;

    if (tid == 0) {
#pragma unroll
        for (int s = 0; s < NSTG; ++s) {
            mbar_init(mb + 16 * s, 16);      // full: 16 warp arrivals
            mbar_init(mb + 16 * s + 8, 16);  // empty: 16 warp arrivals
        }
    }
    __syncthreads();

    // A loader: 4 threads/row, each 16 floats (4 x float4)
    const int arow = tid >> 2;               // 0..127
    const int aq   = tid & 3;
    const float* gA = A + (size_t)(m0 + arow) * NROWS + kb + aq * 16;
    const uint32_t arow_off = (uint32_t)arow * 128u;
    const int armask = arow & 7;

    // B loader: 2 threads/row (256 rows), 4 x 16B chunks each
    const int brow = tid >> 1;               // 0..255
    const int bh   = tid & 1;
    const __half* gB = g_BhT + (size_t)brow * NROWS + kb + bh * 32;
    const uint32_t brow_off = 16384u + (uint32_t)brow * 128u;
    const int brmask = brow & 7;

    float4 pf[4];

#define LDGA(t)                                                                \
    do {                                                                       \
        const float4* p = (const float4*)(gA + (size_t)(t) * BK2);             \
        _Pragma("unroll") for (int j = 0; j < 4; ++j) pf[j] = __ldg(p + j);    \
    } while (0)
#define STSA(stg)                                                              \
    do {                                                                       \
        uint32_t db = smem + (stg) * STG2 + arow_off;                          \
        _Pragma("unroll") for (int c = 0; c < 2; ++c) {                        \
            __half2 h0 = __floats2half2_rn(pf[2 * c].x, pf[2 * c].y);          \
            __half2 h1 = __floats2half2_rn(pf[2 * c].z, pf[2 * c].w);          \
            __half2 h2 = __floats2half2_rn(pf[2 * c + 1].x, pf[2 * c + 1].y);  \
            __half2 h3 = __floats2half2_rn(pf[2 * c + 1].z, pf[2 * c + 1].w);  \
            uint32_t ch = (uint32_t)((aq * 2 + c) ^ armask);                   \
            sts128(db + ch * 16u, *(uint32_t*)&h0, *(uint32_t*)&h1,            \
                   *(uint32_t*)&h2, *(uint32_t*)&h3);                          \
        }                                                                      \
    } while (0)
#define CPB(stg, t)                                                            \
    do {                                                                       \
        uint32_t db = smem + (stg) * STG2 + brow_off;                          \
        const __half* p = gB + (size_t)(t) * BK2;                              \
        _Pragma("unroll") for (int j = 0; j < 4; ++j) {                        \
            uint32_t ch = (uint32_t)((bh * 4 + j) ^ brmask);                   \
            cp16(db + ch * 16u, p + j * 8);                                    \
        }                                                                      \
    } while (0)

    float acc[4][4][4];
#pragma unroll
    for (int i = 0; i < 4; ++i)
#pragma unroll
        for (int j = 0; j < 4; ++j)
#pragma unroll
            for (int q = 0; q < 4; ++q) acc[i][j][q] = 0.0f;

    const int lr8 = (lane & 7) + ((lane >> 3) & 1) * 8;
    uint32_t rowA[4], rowB[2];
#pragma unroll
    for (int mt = 0; mt < 4; ++mt) rowA[mt] = (uint32_t)(wm + mt * 16 + lr8) * 128u;
#pragma unroll
    for (int i = 0; i < 2; ++i)
        rowB[i] = 16384u + (uint32_t)(wn + i * 16 + lr8) * 128u;
    const uint32_t lmask = (uint32_t)(lane & 7);
    const uint32_t khalf = (uint32_t)(lane >> 4);

    // one ks step (16 HMMA) from stage stg
#define CSTEP(stg, ks)                                                         \
    do {                                                                       \
        uint32_t sb0 = smem + (stg) * STG2;                                    \
        uint32_t pa = (((ks) * 2 + khalf) ^ lmask) * 16u;                      \
        uint32_t a[4][4], b[2][4];                                             \
        _Pragma("unroll") for (int mt = 0; mt < 4; ++mt)                       \
            ldmx4(a[mt], sb0 + rowA[mt] + pa);                                 \
        _Pragma("unroll") for (int i = 0; i < 2; ++i)                          \
            ldmx4(b[i], sb0 + rowB[i] + pa);                                   \
        _Pragma("unroll") for (int mt = 0; mt < 4; ++mt)                       \
            _Pragma("unroll") for (int j = 0; j < 4; ++j)                      \
                mma16816(acc[mt][j], a[mt], b[j >> 1][j & 1],                  \
                         b[j >> 1][2 + (j & 1)]);                              \
    } while (0)

    const int T = KLEN / BK2;  // 64

    // prologue: fill tiles 0..2 (stages 0..2), publish after own cps drain
    LDGA(0); STSA(0); CPB(0, 0); cp_commit();
    LDGA(1); STSA(1); CPB(1, 1); cp_commit();
    LDGA(2); STSA(2); CPB(2, 2); cp_commit();
    cp_wait0();
    __syncwarp();
    if (elect_one()) {
        mbar_arrive(mb + 0);
        mbar_arrive(mb + 16);
        mbar_arrive(mb + 32);
    }

    for (int t = 0; t < T; ++t) {
        const int s  = t & 3;
        const int tp = t + 3;
        const int sp = tp & 3;

        if (tp < T) LDGA(tp);

        mbar_wait(mb + 16 * s, (uint32_t)((t >> 2) & 1));   // full[s]

        CSTEP(s, 0);
        CSTEP(s, 1);

        if (tp < T) {
            if (tp >= NSTG)
                mbar_wait(mb + 16 * sp + 8, (uint32_t)(((tp >> 2) - 1) & 1));
            STSA(sp);
            CPB(sp, tp);
        }
        cp_commit();   // one group per iteration, possibly empty

        CSTEP(s, 2);
        CSTEP(s, 3);

        __syncwarp();
        if (elect_one()) mbar_arrive(mb + 16 * s + 8);      // empty[s]

        // publish previous iteration's fill (tile t+2) once own cps drained
        if (t >= 1 && t + 2 < T) {
            cp_wait1();
            __syncwarp();
            if (elect_one()) mbar_arrive(mb + 16 * ((t + 2) & 3));
        }
    }

    // epilogue -> fp32 partials
    float* Pz = P + (size_t)blockIdx.y * NROWS * NCH;
    const int er = lane >> 2;
    const int ec = (lane & 3) * 2;
#pragma unroll
    for (int mt = 0; mt < 4; ++mt) {
        const int r0 = m0 + wm + mt * 16 + er;
#pragma unroll
        for (int j = 0; j < 4; ++j) {
            const int c = wn + j * 8 + ec;
            float* a = acc[mt][j];
            *(float2*)(Pz + (size_t)r0 * NCH + c) = make_float2(a[0], a[1]);
            *(float2*)(Pz + (size_t)(r0 + 8) * NCH + c) = make_float2(a[2], a[3]);
        }
    }
#undef LDGA
#undef STSA
#undef CPB
#undef CSTEP
}

// ---------------- launch ----------------
extern "C" void kernel_launch(void* const* d_in, const int* in_sizes, int n_in,
                              void* d_out, int out_size) {
    (void)in_sizes; (void)n_in; (void)out_size;
    const float* A = (const float*)d_in[0];
    const float* D = (const float*)d_in[1];
    const float* H = (const float*)d_in[2];
    const float* W = (const float*)d_in[3];
    float* out = (float*)d_out;

    __half *pWhT, *pBhT;
    float* pP;
    cudaGetSymbolAddress((void**)&pWhT, g_WhT);
    cudaGetSymbolAddress((void**)&pBhT, g_BhT);
    cudaGetSymbolAddress((void**)&pP, g_P);

    cudaFuncSetAttribute(gemm1_hmma, cudaFuncAttributeMaxDynamicSharedMemorySize,
                         SMEM_SZ);
    cudaFuncSetAttribute(gemm2_hmma, cudaFuncAttributeMaxDynamicSharedMemorySize,
                         SMEM2);

    compute_d_kernel<<<NROWS / 256, 256>>>(D);
    convW_kernel<<<NCH, NCH>>>(W);

    // BhT[n][m] = d[m] * (W^T @ H^T)[n][m]
    gemm1_hmma<<<dim3(NROWS / BN, NCH / BM), NTHREADS, SMEM_SZ>>>(
        H, NCH, pWhT, NCH, NCH / BK, pBhT);

    // P[z] = A[:, z-slice] @ B[z-slice, :]
    gemm2_hmma<<<dim3(NROWS / BM2, KSPLIT), NTH2, SMEM2>>>(A, pP);

    // out = diag(d) * (P0 + P1)
    reduce_kernel<<<(NROWS * NCH) / 1024, 256>>>(out);
}